// round 11
// baseline (speedup 1.0000x reference)
#include <cuda_runtime.h>
#include <cuda_bf16.h>
#include <math.h>
#include <stdint.h>

// ---------------- problem constants ----------------
#define B_   2
#define S_   512
#define T_   1024
#define H_   1024
#define NH_  16
#define HD_  64
#define E_   32
#define D_   8
#define K_   6
#define KD_  3
#define I_   1536
#define EPS_ 1e-5f
#define TK_  (T_*K_)

// ---------------- device scratch ----------------
__device__ float g_qkv [T_*3*H_];
__device__ float g_attn[T_*H_];
__device__ float g_tmp [2*T_*H_];     // split-K partials for Wo
__device__ float g_h1  [T_*H_];
__device__ float g_sgu [2*T_*2*I_];
__device__ float g_sdwn[2*T_*H_];
__device__ float g_rgu [TK_*2*I_];
__device__ float g_rdwn[TK_*H_];

__device__ float g_Pi  [E_];
__device__ float g_comm[D_];
__device__ int   g_cnt [E_];
__device__ int   g_off [E_];
__device__ int   g_cur [E_];
__device__ int   g_sel_e[TK_];
__device__ float g_sel_w[TK_];
__device__ int   g_ltok [TK_];
__device__ int   g_lslot[TK_];
__device__ float g_lw   [TK_];

// ---------------- helpers ----------------
__device__ __forceinline__ float silu1(float g) { return g / (1.f + expf(-g)); }

__device__ __forceinline__ float block_sum256(float v) {
    __shared__ float red[8];
    __shared__ float tot;
    #pragma unroll
    for (int o = 16; o; o >>= 1) v += __shfl_xor_sync(0xffffffffu, v, o);
    if ((threadIdx.x & 31) == 0) red[threadIdx.x >> 5] = v;
    __syncthreads();
    if (threadIdx.x < 8) {
        float s = red[threadIdx.x];
        #pragma unroll
        for (int o = 4; o; o >>= 1) s += __shfl_xor_sync(0xffu, s, o);
        if (threadIdx.x == 0) tot = s;
    }
    __syncthreads();
    return tot;
}

// ---------------- mma primitives ----------------
__device__ __forceinline__ uint32_t smem_u32(const void* p) {
    return (uint32_t)__cvta_generic_to_shared(p);
}
__device__ __forceinline__ void ldm_x4t(uint32_t r[4], uint32_t addr) {
    asm volatile("ldmatrix.sync.aligned.m8n8.x4.trans.shared.b16 {%0,%1,%2,%3},[%4];"
        : "=r"(r[0]), "=r"(r[1]), "=r"(r[2]), "=r"(r[3]) : "r"(addr));
}
__device__ __forceinline__ void mma_bf16(float c[4], const uint32_t a[4],
                                         uint32_t b0, uint32_t b1) {
    asm volatile(
        "mma.sync.aligned.m16n8k16.row.col.f32.bf16.bf16.f32 "
        "{%0,%1,%2,%3},{%4,%5,%6,%7},{%8,%9},{%0,%1,%2,%3};"
        : "+f"(c[0]), "+f"(c[1]), "+f"(c[2]), "+f"(c[3])
        : "r"(a[0]), "r"(a[1]), "r"(a[2]), "r"(a[3]), "r"(b0), "r"(b1));
}

// fp32 -> bf16 hi/lo split
__device__ __forceinline__ void split2u(float2 v, uint32_t& h, uint32_t& l) {
    __nv_bfloat162 hb = __float22bfloat162_rn(v);
    float2 r = make_float2(v.x - __bfloat162float(hb.x), v.y - __bfloat162float(hb.y));
    __nv_bfloat162 lb = __float22bfloat162_rn(r);
    h = *(uint32_t*)&hb; l = *(uint32_t*)&lb;
}
__device__ __forceinline__ void split8(const float* v, uint4& hi, uint4& lo) {
    uint32_t h[4], l[4];
    #pragma unroll
    for (int i = 0; i < 4; i++) split2u(make_float2(v[2*i], v[2*i+1]), h[i], l[i]);
    hi = *(uint4*)h; lo = *(uint4*)l;
}

// B smem: 2 stages x 2 fields x 32 rows x BPX halfs (pitch conflict-free for ldm trans)
#define BPX 264
#define BFLD (32*BPX)
#define SMEM_B ((size_t)2*2*BFLD*2)   // 67584 bytes

// Build A fragment (m16k16, row-major) for rows (p0: r, p1: r+8) at k column kc.
// AM: 0 plain, 2 swiglu (gate at +0, up at +I_)
template<int AM>
__device__ __forceinline__ void build_afrag(const float* p0, const float* p1,
                                            bool ok0, bool ok1, int kc,
                                            uint32_t ah[4], uint32_t al[4]) {
    float2 x[4];
    if (AM == 2) {
        #pragma unroll
        for (int i = 0; i < 4; i++) {
            const float* p = (i & 1) ? p1 : p0;
            bool ok = (i & 1) ? ok1 : ok0;
            int c = kc + (i >> 1) * 8;
            if (ok) {
                float2 g = *(const float2*)(p + c);
                float2 u = *(const float2*)(p + c + I_);
                x[i] = make_float2(silu1(g.x) * u.x, silu1(g.y) * u.y);
            } else x[i] = make_float2(0.f, 0.f);
        }
    } else {
        x[0] = ok0 ? *(const float2*)(p0 + kc)     : make_float2(0.f, 0.f);
        x[1] = ok1 ? *(const float2*)(p1 + kc)     : make_float2(0.f, 0.f);
        x[2] = ok0 ? *(const float2*)(p0 + kc + 8) : make_float2(0.f, 0.f);
        x[3] = ok1 ? *(const float2*)(p1 + kc + 8) : make_float2(0.f, 0.f);
    }
    #pragma unroll
    for (int i = 0; i < 4; i++) split2u(x[i], ah[i], al[i]);
}

// ============================================================================
// Unified mma.sync GEMM: block 64x256, warp 32x64 (2m x 4n), BK=32, 3-term
// bf16 split. A operands register-direct from global (no A smem).
// AM: 0 plain rows, 1 gather rows via g_ltok, 2 swiglu rows
// CM: 0 plain store (z-batched), 1 store to list rows, 2 weighted scatter
// RT: routed (per-expert cnt/off from z)
// ============================================================================
template<int AM, int CM, bool RT>
__global__ __launch_bounds__(256, 2)
void mt_gemm(const float* __restrict__ A, int aStride, size_t aBatch,
             const float* __restrict__ Bw, size_t bBatch,
             int N, int Kd,
             float* __restrict__ C, size_t cBatch)
{
    const int z = blockIdx.z;
    int cnt = 0x7fffffff, off = 0;
    if (RT) { cnt = g_cnt[z]; off = g_off[z]; }
    const int m0 = blockIdx.y * 64;
    if (RT && m0 >= cnt) return;
    const int n0 = blockIdx.x * 256;

    extern __shared__ __align__(16) __nv_bfloat16 sB[];
    const int tid = threadIdx.x, lane = tid & 31, wid = tid >> 5;
    const int wm = wid & 1, wn = wid >> 1;

    const float* Az = A + (size_t)z * aBatch;
    const float* Bz = Bw + (size_t)z * bBatch;

    // ---- A row pointers (4 rows per thread: wm*32 + {r, r+8, r+16, r+24}) ----
    const int r = lane >> 2;
    const int kq = (lane & 3) * 2;
    const float* ap[4]; bool aok[4];
    #pragma unroll
    for (int j = 0; j < 4; j++) {
        int rowl = wm * 32 + ((j >> 1) * 16) + ((j & 1) * 8) + r;
        int grow = m0 + rowl;
        if (AM == 1) {
            bool ok = grow < cnt;
            int tok = ok ? g_ltok[off + grow] : 0;
            aok[j] = ok;
            ap[j] = Az + (size_t)tok * aStride;
        } else if (AM == 2 && RT) {
            bool ok = grow < cnt;
            aok[j] = ok;
            ap[j] = Az + (size_t)(off + (ok ? grow : 0)) * aStride;
        } else {
            aok[j] = true;
            ap[j] = Az + (size_t)grow * aStride;
        }
    }

    // ---- B staging ids: thread covers k-row (tid>>3), 32 n at (tid&7)*32 ----
    const int bkrow = tid >> 3;
    const int bnb = (tid & 7) * 32;
    const float* Bg = Bz + (size_t)bkrow * N + n0 + bnb;
    const int bkr = lane & 15, bnl = (lane >> 4) * 8;

    float acc[16][4];
    #pragma unroll
    for (int i = 0; i < 16; i++)
        #pragma unroll
        for (int j = 0; j < 4; j++) acc[i][j] = 0.f;

    float4 pb[4];
    // prologue: stage k-tile 0 into stage 0 (both 16-col chunks)
    #pragma unroll
    for (int c = 0; c < 2; c++) {
        const float* bp = Bg + c * 16;
        pb[0] = *(const float4*)bp;      pb[1] = *(const float4*)(bp + 4);
        pb[2] = *(const float4*)(bp + 8); pb[3] = *(const float4*)(bp + 12);
        uint4 h0, l0, h1, l1;
        split8((const float*)&pb[0], h0, l0);
        split8((const float*)&pb[2], h1, l1);
        __nv_bfloat16* dh = sB + 0 * BFLD + bkrow * BPX + bnb + c * 16;
        __nv_bfloat16* dl = sB + 1 * BFLD + bkrow * BPX + bnb + c * 16;
        *(uint4*)dh = h0; *(uint4*)(dh + 8) = h1;
        *(uint4*)dl = l0; *(uint4*)(dl + 8) = l1;
    }
    __syncthreads();

    const int nK = Kd >> 5;
    for (int kt = 0; kt < nK; kt++) {
        const int s = kt & 1;
        const bool nxt = (kt + 1) < nK;
        const __nv_bfloat16* Bh = sB + (s * 2 + 0) * BFLD;
        const __nv_bfloat16* Bl = sB + (s * 2 + 1) * BFLD;
        __nv_bfloat16* dBh = sB + ((s ^ 1) * 2 + 0) * BFLD + bkrow * BPX + bnb;
        __nv_bfloat16* dBl = sB + ((s ^ 1) * 2 + 1) * BFLD + bkrow * BPX + bnb;

        if (nxt) {
            const float* bp = Bg + (size_t)((kt + 1) << 5) * N;
            pb[0] = *(const float4*)bp;      pb[1] = *(const float4*)(bp + 4);
            pb[2] = *(const float4*)(bp + 8); pb[3] = *(const float4*)(bp + 12);
        }

        // ---- k16 substep 0 ----
        {
            uint32_t ah[2][4], al[2][4];
            int kcol = (kt << 5) + kq;
            build_afrag<AM>(ap[0], ap[1], aok[0], aok[1], kcol, ah[0], al[0]);
            build_afrag<AM>(ap[2], ap[3], aok[2], aok[3], kcol, ah[1], al[1]);
            #pragma unroll
            for (int nf2 = 0; nf2 < 4; nf2++) {
                int o = bkr * BPX + wn * 64 + nf2 * 16 + bnl;
                uint32_t bh[4], bl4[4];
                ldm_x4t(bh,  smem_u32(Bh + o));
                ldm_x4t(bl4, smem_u32(Bl + o));
                #pragma unroll
                for (int mf = 0; mf < 2; mf++) {
                    float* c0 = acc[mf * 8 + nf2 * 2 + 0];
                    float* c1 = acc[mf * 8 + nf2 * 2 + 1];
                    mma_bf16(c0, ah[mf], bh[0],  bh[1]);
                    mma_bf16(c0, ah[mf], bl4[0], bl4[1]);
                    mma_bf16(c0, al[mf], bh[0],  bh[1]);
                    mma_bf16(c1, ah[mf], bh[2],  bh[3]);
                    mma_bf16(c1, ah[mf], bl4[2], bl4[3]);
                    mma_bf16(c1, al[mf], bh[2],  bh[3]);
                }
            }
        }

        if (nxt) {  // store chunk0 to next stage, load chunk1
            uint4 h0, l0, h1, l1;
            split8((const float*)&pb[0], h0, l0);
            split8((const float*)&pb[2], h1, l1);
            *(uint4*)dBh = h0; *(uint4*)(dBh + 8) = h1;
            *(uint4*)dBl = l0; *(uint4*)(dBl + 8) = l1;
            const float* bp = Bg + (size_t)((kt + 1) << 5) * N + 16;
            pb[0] = *(const float4*)bp;      pb[1] = *(const float4*)(bp + 4);
            pb[2] = *(const float4*)(bp + 8); pb[3] = *(const float4*)(bp + 12);
        }

        // ---- k16 substep 1 ----
        {
            uint32_t ah[2][4], al[2][4];
            int kcol = (kt << 5) + 16 + kq;
            build_afrag<AM>(ap[0], ap[1], aok[0], aok[1], kcol, ah[0], al[0]);
            build_afrag<AM>(ap[2], ap[3], aok[2], aok[3], kcol, ah[1], al[1]);
            #pragma unroll
            for (int nf2 = 0; nf2 < 4; nf2++) {
                int o = (16 + bkr) * BPX + wn * 64 + nf2 * 16 + bnl;
                uint32_t bh[4], bl4[4];
                ldm_x4t(bh,  smem_u32(Bh + o));
                ldm_x4t(bl4, smem_u32(Bl + o));
                #pragma unroll
                for (int mf = 0; mf < 2; mf++) {
                    float* c0 = acc[mf * 8 + nf2 * 2 + 0];
                    float* c1 = acc[mf * 8 + nf2 * 2 + 1];
                    mma_bf16(c0, ah[mf], bh[0],  bh[1]);
                    mma_bf16(c0, ah[mf], bl4[0], bl4[1]);
                    mma_bf16(c0, al[mf], bh[0],  bh[1]);
                    mma_bf16(c1, ah[mf], bh[2],  bh[3]);
                    mma_bf16(c1, ah[mf], bl4[2], bl4[3]);
                    mma_bf16(c1, al[mf], bh[2],  bh[3]);
                }
            }
        }

        if (nxt) {  // store chunk1 to next stage
            uint4 h0, l0, h1, l1;
            split8((const float*)&pb[0], h0, l0);
            split8((const float*)&pb[2], h1, l1);
            *(uint4*)(dBh + 16) = h0; *(uint4*)(dBh + 24) = h1;
            *(uint4*)(dBl + 16) = l0; *(uint4*)(dBl + 24) = l1;
        }
        __syncthreads();
    }

    // ---- epilogue ----
    #pragma unroll
    for (int mf = 0; mf < 2; mf++)
        #pragma unroll
        for (int nf = 0; nf < 8; nf++) {
            float* c = acc[mf * 8 + nf];
            int lr0 = m0 + wm * 32 + mf * 16 + (lane >> 2);
            int col = n0 + wn * 64 + nf * 8 + (lane & 3) * 2;
            if (CM == 0) {
                float* p0 = C + (size_t)z * cBatch + (size_t)lr0 * N + col;
                float* p1 = C + (size_t)z * cBatch + (size_t)(lr0 + 8) * N + col;
                p0[0] = c[0]; p0[1] = c[1]; p1[0] = c[2]; p1[1] = c[3];
            } else if (CM == 1) {
                if (lr0 < cnt) {
                    float* p = C + (size_t)(off + lr0) * N + col;
                    p[0] = c[0]; p[1] = c[1];
                }
                if (lr0 + 8 < cnt) {
                    float* p = C + (size_t)(off + lr0 + 8) * N + col;
                    p[0] = c[2]; p[1] = c[3];
                }
            } else {
                if (lr0 < cnt) {
                    int slot = g_lslot[off + lr0];
                    float w  = g_lw[off + lr0];
                    float* p = C + (size_t)slot * H_ + col;
                    p[0] = w * c[0]; p[1] = w * c[1];
                }
                if (lr0 + 8 < cnt) {
                    int slot = g_lslot[off + lr0 + 8];
                    float w  = g_lw[off + lr0 + 8];
                    float* p = C + (size_t)slot * H_ + col;
                    p[0] = w * c[2]; p[1] = w * c[3];
                }
            }
        }
}

// ---------------- flash attention (fp32, validated) --------------------------
__global__ __launch_bounds__(256)
void flash_attn() {
    __shared__ float Qs[64][68];
    __shared__ float Ks[32][68];
    __shared__ float Vs[32][68];
    __shared__ float Ps[64][36];
    const int q0 = blockIdx.x * 64;
    const int h  = blockIdx.y;
    const int b  = blockIdx.z;
    const int tid = threadIdx.x;
    const size_t rs = 3 * H_;
    const float* qb = g_qkv + (size_t)b * S_ * rs + (size_t)h * HD_;
    const float* kb = qb + H_;
    const float* vb = qb + 2 * H_;
    const float scale = 0.125f;
    for (int i = tid; i < 64 * 64; i += 256) {
        int rr = i >> 6, d = i & 63;
        Qs[rr][d] = qb[(size_t)(q0 + rr) * rs + d] * scale;
    }
    const int rr = tid >> 2;
    const int c4 = tid & 3;
    float m_i = -1e30f, l_i = 0.f;
    float acc[16];
    #pragma unroll
    for (int i = 0; i < 16; i++) acc[i] = 0.f;
    __syncthreads();
    for (int kt = 0; kt < S_; kt += 32) {
        for (int i = tid; i < 32 * 64; i += 256) {
            int r2 = i >> 6, d = i & 63;
            Ks[r2][d] = kb[(size_t)(kt + r2) * rs + d];
            Vs[r2][d] = vb[(size_t)(kt + r2) * rs + d];
        }
        __syncthreads();
        float sc[8];
        float mx = -1e30f;
        const float4* qrow = (const float4*)&Qs[rr][0];
        #pragma unroll
        for (int jj = 0; jj < 8; jj++) {
            int j = c4 * 8 + jj;
            const float4* krow = (const float4*)&Ks[j][0];
            float sv = 0.f;
            #pragma unroll
            for (int dv = 0; dv < 16; dv++) {
                float4 a = qrow[dv], bq = krow[dv];
                sv += a.x * bq.x + a.y * bq.y + a.z * bq.z + a.w * bq.w;
            }
            sc[jj] = sv; mx = fmaxf(mx, sv);
        }
        mx = fmaxf(mx, __shfl_xor_sync(0xffffffffu, mx, 1));
        mx = fmaxf(mx, __shfl_xor_sync(0xffffffffu, mx, 2));
        float m_new = fmaxf(m_i, mx);
        float alpha = expf(m_i - m_new);
        float psum = 0.f;
        #pragma unroll
        for (int jj = 0; jj < 8; jj++) {
            float p = expf(sc[jj] - m_new);
            Ps[rr][c4 * 8 + jj] = p;
            psum += p;
        }
        psum += __shfl_xor_sync(0xffffffffu, psum, 1);
        psum += __shfl_xor_sync(0xffffffffu, psum, 2);
        l_i = l_i * alpha + psum;
        m_i = m_new;
        #pragma unroll
        for (int i = 0; i < 16; i++) acc[i] *= alpha;
        __syncwarp();
        #pragma unroll
        for (int i = 0; i < 16; i++) {
            int d = c4 * 16 + i;
            float s = 0.f;
            #pragma unroll 8
            for (int j = 0; j < 32; j++) s += Ps[rr][j] * Vs[j][d];
            acc[i] += s;
        }
        __syncthreads();
    }
    float inv = 1.f / l_i;
    float* ob = g_attn + (size_t)((b * S_ + q0 + rr)) * H_ + (size_t)h * HD_;
    #pragma unroll
    for (int i = 0; i < 16; i++) ob[c4 * 16 + i] = acc[i] * inv;
}

// ---------------- residual + rmsnorm over 3-way sum --------------------------
__global__ __launch_bounds__(256)
void resid_rms3(const float* __restrict__ a, const float* __restrict__ b0,
                const float* __restrict__ b1, float* __restrict__ o) {
    const int t = blockIdx.x;
    float v[4]; float ss = 0.f;
    #pragma unroll
    for (int i = 0; i < 4; i++) {
        int j = i * 256 + threadIdx.x;
        float s = a[(size_t)t * H_ + j] + b0[(size_t)t * H_ + j] + b1[(size_t)t * H_ + j];
        v[i] = s; ss += s * s;
    }
    ss = block_sum256(ss);
    float inv = rsqrtf(ss * (1.f / H_) + EPS_);
    #pragma unroll
    for (int i = 0; i < 4; i++) {
        int j = i * 256 + threadIdx.x;
        o[(size_t)t * H_ + j] = v[i] * inv;
    }
}

// ---------------- routing ----------------------------------------------------
__global__ void zero_small() {
    int i = threadIdx.x;
    if (i < E_) { g_Pi[i] = 0.f; g_cnt[i] = 0; }
    if (i < D_)   g_comm[i] = 0.f;
}

__global__ void routing_kernel(const float* __restrict__ Wr) {
    const int t = blockIdx.x;
    const int e = threadIdx.x;
    const float* xr = g_h1 + (size_t)t * H_;
    float logit = 0.f;
    for (int j = 0; j < H_; j++) logit += xr[j] * Wr[(size_t)j * E_ + e];
    float m = logit;
    #pragma unroll
    for (int o = 16; o; o >>= 1) m = fmaxf(m, __shfl_xor_sync(0xffffffffu, m, o));
    float ex = expf(logit - m);
    float s = ex;
    #pragma unroll
    for (int o = 16; o; o >>= 1) s += __shfl_xor_sync(0xffffffffu, s, o);
    float prob = ex / s;
    atomicAdd(&g_Pi[e], prob);
    __shared__ float sp[E_];
    sp[e] = prob;
    __syncwarp();
    if (e == 0) {
        float ds[D_];
        #pragma unroll
        for (int d = 0; d < D_; d++)
            ds[d] = sp[4*d] + sp[4*d+1] + sp[4*d+2] + sp[4*d+3];
        bool dsel[D_] = {};
        for (int rsel = 0; rsel < KD_; rsel++) {
            int best = -1; float bv = -1e30f;
            for (int d = 0; d < D_; d++)
                if (!dsel[d] && ds[d] > bv) { bv = ds[d]; best = d; }
            dsel[best] = true;
        }
        float masked[E_];
        #pragma unroll
        for (int i = 0; i < E_; i++)
            masked[i] = dsel[i >> 2] ? sp[i] : -1e30f;
        int   iv[K_]; float wv[K_];
        for (int rsel = 0; rsel < K_; rsel++) {
            int best = 0; float bv = -1e31f;
            for (int i = 0; i < E_; i++)
                if (masked[i] > bv) { bv = masked[i]; best = i; }
            iv[rsel] = best; wv[rsel] = bv;
            masked[best] = -1e31f;
        }
        float mm = wv[0];
        float ssum = 0.f;
        #pragma unroll
        for (int rsel = 0; rsel < K_; rsel++) { wv[rsel] = expf(wv[rsel] - mm); ssum += wv[rsel]; }
        bool hit[D_] = {};
        #pragma unroll
        for (int rsel = 0; rsel < K_; rsel++) hit[iv[rsel] >> 2] = true;
        for (int d = 0; d < D_; d++)
            if (hit[d]) atomicAdd(&g_comm[d], 1.0f);
        #pragma unroll
        for (int rsel = 0; rsel < K_; rsel++) {
            int idx = t * K_ + rsel;
            g_sel_e[idx] = iv[rsel];
            g_sel_w[idx] = wv[rsel] / ssum;
            atomicAdd(&g_cnt[iv[rsel]], 1);
        }
    }
}

__global__ void offsets_kernel() {
    if (threadIdx.x == 0) {
        int s = 0;
        for (int e = 0; e < E_; e++) { g_off[e] = s; g_cur[e] = s; s += g_cnt[e]; }
    }
}

__global__ void scatter_kernel() {
    int i = blockIdx.x * 256 + threadIdx.x;
    if (i >= TK_) return;
    int e = g_sel_e[i];
    int pos = atomicAdd(&g_cur[e], 1);
    g_ltok[pos]  = i / K_;
    g_lslot[pos] = i;
    g_lw[pos]    = g_sel_w[i];
}

// ---------------- final combine + rmsnorm + aux -------------------------------
__global__ __launch_bounds__(256)
void final_kernel(float* __restrict__ out) {
    const int t = blockIdx.x;
    float v[4]; float ss = 0.f;
    #pragma unroll
    for (int i = 0; i < 4; i++) {
        int j = i * 256 + threadIdx.x;
        float s = g_h1[(size_t)t * H_ + j]
                + g_sdwn[(size_t)t * H_ + j]
                + g_sdwn[(size_t)(T_ + t) * H_ + j];
        #pragma unroll
        for (int k = 0; k < K_; k++)
            s += g_rdwn[(size_t)(t * K_ + k) * H_ + j];
        v[i] = s; ss += s * s;
    }
    ss = block_sum256(ss);
    float inv = rsqrtf(ss * (1.f / H_) + EPS_);
    #pragma unroll
    for (int i = 0; i < 4; i++) {
        int j = i * 256 + threadIdx.x;
        out[(size_t)t * H_ + j] = v[i] * inv;
    }
}

__global__ void aux_kernel(float* out, int out_size) {
    if (out_size <= T_ * H_) return;
    const float fTK = (float)TK_ + 1e-10f;
    float fi[E_], Pi[E_];
    float s1 = 0.f;
    for (int e = 0; e < E_; e++) {
        fi[e] = (float)g_cnt[e] / fTK;
        Pi[e] = g_Pi[e] / (float)T_;
        s1 += fi[e] * Pi[e];
    }
    float eb = fminf(s1 * 0.003f, 10.f);
    float dP[D_];
    float s2 = 0.f;
    for (int d = 0; d < D_; d++) {
        float df = (fi[4*d] + fi[4*d+1] + fi[4*d+2] + fi[4*d+3]) * 0.25f;
        dP[d]    = Pi[4*d] + Pi[4*d+1] + Pi[4*d+2] + Pi[4*d+3];
        s2 += df * dP[d];
    }
    float db = fminf(s2 * 0.05f, 10.f);
    float s3 = 0.f;
    for (int d = 0; d < D_; d++) {
        float fc = g_comm[d] / ((float)(T_ * KD_) + 1e-10f);
        s3 += fc * dP[d];
    }
    float cb = fminf(s3 * 0.02f, 10.f);
    out[T_ * H_] = eb + db + cb;
}

// ---------------- host driver -------------------------------------------------
extern "C" void kernel_launch(void* const* d_in, const int* in_sizes, int n_in,
                              void* d_out, int out_size) {
    const float* x     = (const float*)d_in[0];
    const float* Wqkv  = (const float*)d_in[1];
    const float* Wo    = (const float*)d_in[2];
    const float* Wgu_s = (const float*)d_in[3];
    const float* Wd_s  = (const float*)d_in[4];
    const float* Wr    = (const float*)d_in[5];
    const float* Wgu   = (const float*)d_in[6];
    const float* Wd    = (const float*)d_in[7];
    float* out = (float*)d_out;

    float *p_qkv, *p_attn, *p_tmp, *p_h1, *p_sgu, *p_sdwn, *p_rgu, *p_rdwn;
    cudaGetSymbolAddress((void**)&p_qkv,  g_qkv);
    cudaGetSymbolAddress((void**)&p_attn, g_attn);
    cudaGetSymbolAddress((void**)&p_tmp,  g_tmp);
    cudaGetSymbolAddress((void**)&p_h1,   g_h1);
    cudaGetSymbolAddress((void**)&p_sgu,  g_sgu);
    cudaGetSymbolAddress((void**)&p_sdwn, g_sdwn);
    cudaGetSymbolAddress((void**)&p_rgu,  g_rgu);
    cudaGetSymbolAddress((void**)&p_rdwn, g_rdwn);

    static bool init_done = false;
    static cudaStream_t s1;
    static cudaEvent_t evFork, evJoin;
    if (!init_done) {
        cudaFuncSetAttribute(mt_gemm<0,0,false>, cudaFuncAttributeMaxDynamicSharedMemorySize, (int)SMEM_B);
        cudaFuncSetAttribute(mt_gemm<2,0,false>, cudaFuncAttributeMaxDynamicSharedMemorySize, (int)SMEM_B);
        cudaFuncSetAttribute(mt_gemm<1,1,true>,  cudaFuncAttributeMaxDynamicSharedMemorySize, (int)SMEM_B);
        cudaFuncSetAttribute(mt_gemm<2,2,true>,  cudaFuncAttributeMaxDynamicSharedMemorySize, (int)SMEM_B);
        cudaStreamCreateWithFlags(&s1, cudaStreamNonBlocking);
        cudaEventCreateWithFlags(&evFork, cudaEventDisableTiming);
        cudaEventCreateWithFlags(&evJoin, cudaEventDisableTiming);
        init_done = true;
    }

    zero_small<<<1, 64>>>();

    // qkv = x @ Wqkv  (M=1024, N=3072, K=1024), grid 12x16
    mt_gemm<0,0,false><<<dim3(12, 16, 1), 256, SMEM_B>>>(
        x, H_, 0, Wqkv, 0, 3 * H_, H_, p_qkv, 0);

    // attention
    flash_attn<<<dim3(S_ / 64, NH_, B_), 256>>>();

    // Wo split-K=2 via batch strides: z offsets A by 512 cols, B by 512 rows
    mt_gemm<0,0,false><<<dim3(4, 16, 2), 256, SMEM_B>>>(
        p_attn, H_, 512, Wo, (size_t)512 * H_, H_, 512, p_tmp, (size_t)T_ * H_);
    resid_rms3<<<T_, 256>>>(x, p_tmp, p_tmp + (size_t)T_ * H_, p_h1);

    // fork: shared experts on s1
    cudaEventRecord(evFork, 0);
    cudaStreamWaitEvent(s1, evFork, 0);
    mt_gemm<0,0,false><<<dim3(12, 16, 2), 256, SMEM_B, s1>>>(
        p_h1, H_, 0, Wgu_s, (size_t)H_ * 2 * I_, 2 * I_, H_, p_sgu, (size_t)T_ * 2 * I_);
    mt_gemm<2,0,false><<<dim3(4, 16, 2), 256, SMEM_B, s1>>>(
        p_sgu, 2 * I_, (size_t)T_ * 2 * I_, Wd_s, (size_t)I_ * H_, H_, I_, p_sdwn, (size_t)T_ * H_);
    cudaEventRecord(evJoin, s1);

    // routed chain on main stream
    routing_kernel<<<T_, 32>>>(Wr);
    offsets_kernel<<<1, 32>>>();
    scatter_kernel<<<(TK_ + 255) / 256, 256>>>();
    mt_gemm<1,1,true><<<dim3(12, 16, E_), 256, SMEM_B>>>(
        p_h1, H_, 0, Wgu, (size_t)H_ * 2 * I_, 2 * I_, H_, p_rgu, 0);
    mt_gemm<2,2,true><<<dim3(4, 16, E_), 256, SMEM_B>>>(
        p_rgu, 2 * I_, 0, Wd, (size_t)I_ * H_, H_, I_, p_rdwn, 0);

    // join and finish
    cudaStreamWaitEvent(0, evJoin, 0);
    final_kernel<<<T_, 256>>>(out);
    aux_kernel<<<1, 1>>>(out, out_size);
}

// round 13
// speedup vs baseline: 1.3570x; 1.3570x over previous
#include <cuda_runtime.h>
#include <cuda_bf16.h>
#include <math.h>
#include <stdint.h>

// ---------------- problem constants ----------------
#define B_   2
#define S_   512
#define T_   1024
#define H_   1024
#define NH_  16
#define HD_  64
#define E_   32
#define D_   8
#define K_   6
#define KD_  3
#define I_   1536
#define EPS_ 1e-5f
#define TK_  (T_*K_)

// ---------------- device scratch ----------------
__device__ float g_qkv [T_*3*H_];
__device__ float g_attn[T_*H_];
__device__ float g_tmp [2*T_*H_];
__device__ float g_h1  [T_*H_];
__device__ float g_sgu [2*T_*2*I_];
__device__ float g_sdwn[2*T_*H_];
__device__ float g_rgu [TK_*2*I_];
__device__ float g_rdwn[TK_*H_];

__device__ float g_Pi  [E_];
__device__ float g_comm[D_];
__device__ int   g_cnt [E_];
__device__ int   g_off [E_];
__device__ int   g_cur [E_];
__device__ int   g_sel_e[TK_];
__device__ float g_sel_w[TK_];
__device__ int   g_ltok [TK_];
__device__ int   g_lslot[TK_];
__device__ float g_lw   [TK_];

// ---------------- helpers ----------------
__device__ __forceinline__ float silu1(float g) { return g / (1.f + expf(-g)); }

__device__ __forceinline__ float block_sum256(float v) {
    __shared__ float red[8];
    __shared__ float tot;
    #pragma unroll
    for (int o = 16; o; o >>= 1) v += __shfl_xor_sync(0xffffffffu, v, o);
    if ((threadIdx.x & 31) == 0) red[threadIdx.x >> 5] = v;
    __syncthreads();
    if (threadIdx.x < 8) {
        float s = red[threadIdx.x];
        #pragma unroll
        for (int o = 4; o; o >>= 1) s += __shfl_xor_sync(0xffu, s, o);
        if (threadIdx.x == 0) tot = s;
    }
    __syncthreads();
    return tot;
}

// ---------------- mma primitives ----------------
__device__ __forceinline__ uint32_t smem_u32(const void* p) {
    return (uint32_t)__cvta_generic_to_shared(p);
}
__device__ __forceinline__ void ldm_x4(uint32_t r[4], uint32_t addr) {
    asm volatile("ldmatrix.sync.aligned.m8n8.x4.shared.b16 {%0,%1,%2,%3},[%4];"
        : "=r"(r[0]), "=r"(r[1]), "=r"(r[2]), "=r"(r[3]) : "r"(addr));
}
__device__ __forceinline__ void ldm_x4t(uint32_t r[4], uint32_t addr) {
    asm volatile("ldmatrix.sync.aligned.m8n8.x4.trans.shared.b16 {%0,%1,%2,%3},[%4];"
        : "=r"(r[0]), "=r"(r[1]), "=r"(r[2]), "=r"(r[3]) : "r"(addr));
}
__device__ __forceinline__ void mma_bf16(float c[4], const uint32_t a[4],
                                         uint32_t b0, uint32_t b1) {
    asm volatile(
        "mma.sync.aligned.m16n8k16.row.col.f32.bf16.bf16.f32 "
        "{%0,%1,%2,%3},{%4,%5,%6,%7},{%8,%9},{%0,%1,%2,%3};"
        : "+f"(c[0]), "+f"(c[1]), "+f"(c[2]), "+f"(c[3])
        : "r"(a[0]), "r"(a[1]), "r"(a[2]), "r"(a[3]), "r"(b0), "r"(b1));
}

// fp32 -> bf16 hi/lo split
__device__ __forceinline__ void split2u(float2 v, uint32_t& h, uint32_t& l) {
    __nv_bfloat162 hb = __float22bfloat162_rn(v);
    float2 r = make_float2(v.x - __bfloat162float(hb.x), v.y - __bfloat162float(hb.y));
    __nv_bfloat162 lb = __float22bfloat162_rn(r);
    h = *(uint32_t*)&hb; l = *(uint32_t*)&lb;
}
__device__ __forceinline__ void split8(const float* v, uint4& hi, uint4& lo) {
    uint32_t h[4], l[4];
    #pragma unroll
    for (int i = 0; i < 4; i++) split2u(make_float2(v[2*i], v[2*i+1]), h[i], l[i]);
    hi = *(uint4*)h; lo = *(uint4*)l;
}
__device__ __forceinline__ void stage8(__nv_bfloat16* dh, __nv_bfloat16* dl,
                                       float4 f0, float4 f1) {
    float v[8] = {f0.x, f0.y, f0.z, f0.w, f1.x, f1.y, f1.z, f1.w};
    uint4 hi, lo; split8(v, hi, lo);
    *(uint4*)dh = hi;
    *(uint4*)dl = lo;
}

// ---------------- smem geometry (dynamic) ------------------------------------
// A: 64 rows x 40-pitch halfs per field-stage; B: 32 rows x 264-pitch halfs.
#define APX 40
#define BPX 264
#define A_STG (64*APX)       // 2560 elems (5120 B)
#define B_STG (32*BPX)       // 8448 elems (16896 B)
#define SMEM_G ((4*A_STG + 4*B_STG) * 2)   // 88064 bytes

// one k16 substep: warp tile 32x64 (wm in {0,1}, wn in {0..3}), 12 ldm / 48 mma
__device__ __forceinline__ void stepN8(
    const __nv_bfloat16* Ah, const __nv_bfloat16* Al,
    const __nv_bfloat16* Bh, const __nv_bfloat16* Bl,
    int ks, int wm, int wn, int lane, float (*acc)[4])
{
    uint32_t ah[2][4], al[2][4];
    const int arow = lane & 15, acol = (lane >> 4) * 8;
    #pragma unroll
    for (int mf = 0; mf < 2; mf++) {
        int off = (wm * 32 + mf * 16 + arow) * APX + ks * 16 + acol;
        ldm_x4(ah[mf], smem_u32(Ah + off));
        ldm_x4(al[mf], smem_u32(Al + off));
    }
    const int bkr = lane & 15, bnl = (lane >> 4) * 8;
    #pragma unroll
    for (int nf2 = 0; nf2 < 4; nf2++) {
        int o = (ks * 16 + bkr) * BPX + wn * 64 + nf2 * 16 + bnl;
        uint32_t bh[4], bl4[4];
        ldm_x4t(bh,  smem_u32(Bh + o));
        ldm_x4t(bl4, smem_u32(Bl + o));
        #pragma unroll
        for (int mf = 0; mf < 2; mf++) {
            float* c0 = acc[mf * 8 + nf2 * 2 + 0];
            float* c1 = acc[mf * 8 + nf2 * 2 + 1];
            mma_bf16(c0, ah[mf], bh[0],  bh[1]);
            mma_bf16(c0, ah[mf], bl4[0], bl4[1]);
            mma_bf16(c0, al[mf], bh[0],  bh[1]);
            mma_bf16(c1, ah[mf], bh[2],  bh[3]);
            mma_bf16(c1, ah[mf], bl4[2], bl4[3]);
            mma_bf16(c1, al[mf], bh[2],  bh[3]);
        }
    }
}

// ============================================================================
// Unified mma.sync GEMM: block 64x256, warp 32x64, BK=32 double-buffered,
// 3-term bf16 split, A and B staged in smem (prefetch in registers).
// AM: 0 plain rows, 1 gather rows via g_ltok, 2 swiglu rows (up at +I_)
// CM: 0 plain store (z-batched), 1 store to list rows, 2 weighted scatter
// RT: routed (per-expert cnt/off from z)
// ============================================================================
template<int AM, int CM, bool RT>
__global__ __launch_bounds__(256, 2)
void mt_gemm(const float* __restrict__ A, int aStride, size_t aBatch,
             const float* __restrict__ Bw, size_t bBatch,
             int N, int Kd,
             float* __restrict__ C, size_t cBatch)
{
    const int z = blockIdx.z;
    int cnt = 0x7fffffff, off = 0;
    if (RT) { cnt = g_cnt[z]; off = g_off[z]; }
    const int m0 = blockIdx.y * 64;
    if (RT && m0 >= cnt) return;
    const int n0 = blockIdx.x * 256;

    extern __shared__ __align__(16) __nv_bfloat16 dsm[];
    __nv_bfloat16* sA = dsm;               // [stage][field] A
    __nv_bfloat16* sBb = dsm + 4 * A_STG;  // [stage][field] B

    const int tid = threadIdx.x, lane = tid & 31, wid = tid >> 5;
    const int wm = wid & 1, wn = wid >> 1;

    const float* Az = A + (size_t)z * aBatch;
    const float* Bz = Bw + (size_t)z * bBatch;

    // A staging: row ar (0..63), cols akc..akc+8 of the 32-k tile
    const int ar = tid >> 2, akc = (tid & 3) * 8;
    bool arow_ok = true;
    const float* Ag;
    if (AM == 1) {
        int tok = (m0 + ar < cnt) ? g_ltok[off + m0 + ar] : -1;
        arow_ok = (tok >= 0);
        Ag = Az + (size_t)(arow_ok ? tok : 0) * aStride + akc;
    } else if (AM == 2 && RT) {
        int grow = m0 + ar;
        arow_ok = grow < cnt;
        Ag = Az + (size_t)(off + (arow_ok ? grow : 0)) * aStride + akc;
    } else {
        Ag = Az + (size_t)(m0 + ar) * aStride + akc;
    }

    // B staging: row bkrow (0..31), cols bnb..bnb+32
    const int bkrow = tid >> 3, bnb = (tid & 7) * 32;
    const float* Bg = Bz + (size_t)bkrow * N + n0 + bnb;

    float acc[16][4];
    #pragma unroll
    for (int i = 0; i < 16; i++)
        #pragma unroll
        for (int j = 0; j < 4; j++) acc[i][j] = 0.f;

    float4 fa0, fa1;
    float4 pb[4];   // contiguous array: split8 reads across pairs safely

    // ---- A load helper (into fa0/fa1) ----
    auto loadA = [&](int k0) {
        if (!arow_ok) { fa0 = fa1 = make_float4(0.f,0.f,0.f,0.f); return; }
        if (AM == 2) {
            float4 g0 = *(const float4*)(Ag + k0);
            float4 g1 = *(const float4*)(Ag + k0 + 4);
            float4 u0 = *(const float4*)(Ag + k0 + I_);
            float4 u1 = *(const float4*)(Ag + k0 + 4 + I_);
            fa0 = make_float4(silu1(g0.x)*u0.x, silu1(g0.y)*u0.y,
                              silu1(g0.z)*u0.z, silu1(g0.w)*u0.w);
            fa1 = make_float4(silu1(g1.x)*u1.x, silu1(g1.y)*u1.y,
                              silu1(g1.z)*u1.z, silu1(g1.w)*u1.w);
        } else {
            fa0 = *(const float4*)(Ag + k0);
            fa1 = *(const float4*)(Ag + k0 + 4);
        }
    };
    auto storeA = [&](int s) {
        stage8(sA + (s*2+0)*A_STG + ar*APX + akc,
               sA + (s*2+1)*A_STG + ar*APX + akc, fa0, fa1);
    };
    auto loadB = [&](int k0, int c) {  // chunk c: 16 cols
        const float* bp = Bg + (size_t)k0 * N + c * 16;
        pb[0] = *(const float4*)bp;       pb[1] = *(const float4*)(bp + 4);
        pb[2] = *(const float4*)(bp + 8); pb[3] = *(const float4*)(bp + 12);
    };
    auto storeB = [&](int s, int c) {
        uint4 h0, l0, h1, l1;
        split8((const float*)&pb[0], h0, l0);
        split8((const float*)&pb[2], h1, l1);
        __nv_bfloat16* dh = sBb + (s*2+0)*B_STG + bkrow*BPX + bnb + c*16;
        __nv_bfloat16* dl = sBb + (s*2+1)*B_STG + bkrow*BPX + bnb + c*16;
        *(uint4*)dh = h0; *(uint4*)(dh + 8) = h1;
        *(uint4*)dl = l0; *(uint4*)(dl + 8) = l1;
    };

    // prologue: stage k-tile 0 into stage 0
    loadA(0); storeA(0);
    loadB(0, 0); storeB(0, 0);
    loadB(0, 1); storeB(0, 1);
    __syncthreads();

    const int nK = Kd >> 5;
    for (int kt = 0; kt < nK; kt++) {
        const int s = kt & 1, nb = s ^ 1;
        const bool nxt = (kt + 1) < nK;
        const __nv_bfloat16* Ah = sA + (s*2+0)*A_STG;
        const __nv_bfloat16* Al = sA + (s*2+1)*A_STG;
        const __nv_bfloat16* Bh = sBb + (s*2+0)*B_STG;
        const __nv_bfloat16* Bl = sBb + (s*2+1)*B_STG;

        if (nxt) { int k0 = (kt + 1) << 5; loadA(k0); loadB(k0, 0); }
        stepN8(Ah, Al, Bh, Bl, 0, wm, wn, lane, acc);
        if (nxt) {
            storeA(nb); storeB(nb, 0);
            int k0 = (kt + 1) << 5; loadB(k0, 1);
        }
        stepN8(Ah, Al, Bh, Bl, 1, wm, wn, lane, acc);
        if (nxt) storeB(nb, 1);
        __syncthreads();
    }

    // ---- epilogue ----
    #pragma unroll
    for (int mf = 0; mf < 2; mf++)
        #pragma unroll
        for (int nf = 0; nf < 8; nf++) {
            float* c = acc[mf * 8 + nf];
            int lr0 = m0 + wm * 32 + mf * 16 + (lane >> 2);
            int col = n0 + wn * 64 + nf * 8 + (lane & 3) * 2;
            if (CM == 0) {
                float* p0 = C + (size_t)z * cBatch + (size_t)lr0 * N + col;
                float* p1 = C + (size_t)z * cBatch + (size_t)(lr0 + 8) * N + col;
                p0[0] = c[0]; p0[1] = c[1]; p1[0] = c[2]; p1[1] = c[3];
            } else if (CM == 1) {
                if (lr0 < cnt) {
                    float* p = C + (size_t)(off + lr0) * N + col;
                    p[0] = c[0]; p[1] = c[1];
                }
                if (lr0 + 8 < cnt) {
                    float* p = C + (size_t)(off + lr0 + 8) * N + col;
                    p[0] = c[2]; p[1] = c[3];
                }
            } else {
                if (lr0 < cnt) {
                    int slot = g_lslot[off + lr0];
                    float w  = g_lw[off + lr0];
                    float* p = C + (size_t)slot * H_ + col;
                    p[0] = w * c[0]; p[1] = w * c[1];
                }
                if (lr0 + 8 < cnt) {
                    int slot = g_lslot[off + lr0 + 8];
                    float w  = g_lw[off + lr0 + 8];
                    float* p = C + (size_t)slot * H_ + col;
                    p[0] = w * c[2]; p[1] = w * c[3];
                }
            }
        }
}

// ---------------- flash attention (fp32, validated) --------------------------
__global__ __launch_bounds__(256)
void flash_attn() {
    __shared__ float Qs[64][68];
    __shared__ float Ks[32][68];
    __shared__ float Vs[32][68];
    __shared__ float Ps[64][36];
    const int q0 = blockIdx.x * 64;
    const int h  = blockIdx.y;
    const int b  = blockIdx.z;
    const int tid = threadIdx.x;
    const size_t rs = 3 * H_;
    const float* qb = g_qkv + (size_t)b * S_ * rs + (size_t)h * HD_;
    const float* kb = qb + H_;
    const float* vb = qb + 2 * H_;
    const float scale = 0.125f;
    for (int i = tid; i < 64 * 64; i += 256) {
        int rr = i >> 6, d = i & 63;
        Qs[rr][d] = qb[(size_t)(q0 + rr) * rs + d] * scale;
    }
    const int rr = tid >> 2;
    const int c4 = tid & 3;
    float m_i = -1e30f, l_i = 0.f;
    float acc[16];
    #pragma unroll
    for (int i = 0; i < 16; i++) acc[i] = 0.f;
    __syncthreads();
    for (int kt = 0; kt < S_; kt += 32) {
        for (int i = tid; i < 32 * 64; i += 256) {
            int r2 = i >> 6, d = i & 63;
            Ks[r2][d] = kb[(size_t)(kt + r2) * rs + d];
            Vs[r2][d] = vb[(size_t)(kt + r2) * rs + d];
        }
        __syncthreads();
        float sc[8];
        float mx = -1e30f;
        const float4* qrow = (const float4*)&Qs[rr][0];
        #pragma unroll
        for (int jj = 0; jj < 8; jj++) {
            int j = c4 * 8 + jj;
            const float4* krow = (const float4*)&Ks[j][0];
            float sv = 0.f;
            #pragma unroll
            for (int dv = 0; dv < 16; dv++) {
                float4 a = qrow[dv], bq = krow[dv];
                sv += a.x * bq.x + a.y * bq.y + a.z * bq.z + a.w * bq.w;
            }
            sc[jj] = sv; mx = fmaxf(mx, sv);
        }
        mx = fmaxf(mx, __shfl_xor_sync(0xffffffffu, mx, 1));
        mx = fmaxf(mx, __shfl_xor_sync(0xffffffffu, mx, 2));
        float m_new = fmaxf(m_i, mx);
        float alpha = expf(m_i - m_new);
        float psum = 0.f;
        #pragma unroll
        for (int jj = 0; jj < 8; jj++) {
            float p = expf(sc[jj] - m_new);
            Ps[rr][c4 * 8 + jj] = p;
            psum += p;
        }
        psum += __shfl_xor_sync(0xffffffffu, psum, 1);
        psum += __shfl_xor_sync(0xffffffffu, psum, 2);
        l_i = l_i * alpha + psum;
        m_i = m_new;
        #pragma unroll
        for (int i = 0; i < 16; i++) acc[i] *= alpha;
        __syncwarp();
        #pragma unroll
        for (int i = 0; i < 16; i++) {
            int d = c4 * 16 + i;
            float s = 0.f;
            #pragma unroll 8
            for (int j = 0; j < 32; j++) s += Ps[rr][j] * Vs[j][d];
            acc[i] += s;
        }
        __syncthreads();
    }
    float inv = 1.f / l_i;
    float* ob = g_attn + (size_t)((b * S_ + q0 + rr)) * H_ + (size_t)h * HD_;
    #pragma unroll
    for (int i = 0; i < 16; i++) ob[c4 * 16 + i] = acc[i] * inv;
}

// ---------------- residual + rmsnorm over 3-way sum --------------------------
__global__ __launch_bounds__(256)
void resid_rms3(const float* __restrict__ a, const float* __restrict__ b0,
                const float* __restrict__ b1, float* __restrict__ o) {
    const int t = blockIdx.x;
    float v[4]; float ss = 0.f;
    #pragma unroll
    for (int i = 0; i < 4; i++) {
        int j = i * 256 + threadIdx.x;
        float s = a[(size_t)t * H_ + j] + b0[(size_t)t * H_ + j] + b1[(size_t)t * H_ + j];
        v[i] = s; ss += s * s;
    }
    ss = block_sum256(ss);
    float inv = rsqrtf(ss * (1.f / H_) + EPS_);
    #pragma unroll
    for (int i = 0; i < 4; i++) {
        int j = i * 256 + threadIdx.x;
        o[(size_t)t * H_ + j] = v[i] * inv;
    }
}

// ---------------- routing ----------------------------------------------------
__global__ void zero_small() {
    int i = threadIdx.x;
    if (i < E_) { g_Pi[i] = 0.f; g_cnt[i] = 0; }
    if (i < D_)   g_comm[i] = 0.f;
}

__global__ void routing_kernel(const float* __restrict__ Wr) {
    const int t = blockIdx.x;
    const int e = threadIdx.x;
    const float* xr = g_h1 + (size_t)t * H_;
    float logit = 0.f;
    for (int j = 0; j < H_; j++) logit += xr[j] * Wr[(size_t)j * E_ + e];
    float m = logit;
    #pragma unroll
    for (int o = 16; o; o >>= 1) m = fmaxf(m, __shfl_xor_sync(0xffffffffu, m, o));
    float ex = expf(logit - m);
    float s = ex;
    #pragma unroll
    for (int o = 16; o; o >>= 1) s += __shfl_xor_sync(0xffffffffu, s, o);
    float prob = ex / s;
    atomicAdd(&g_Pi[e], prob);
    __shared__ float sp[E_];
    sp[e] = prob;
    __syncwarp();
    if (e == 0) {
        float ds[D_];
        #pragma unroll
        for (int d = 0; d < D_; d++)
            ds[d] = sp[4*d] + sp[4*d+1] + sp[4*d+2] + sp[4*d+3];
        bool dsel[D_] = {};
        for (int rsel = 0; rsel < KD_; rsel++) {
            int best = -1; float bv = -1e30f;
            for (int d = 0; d < D_; d++)
                if (!dsel[d] && ds[d] > bv) { bv = ds[d]; best = d; }
            dsel[best] = true;
        }
        float masked[E_];
        #pragma unroll
        for (int i = 0; i < E_; i++)
            masked[i] = dsel[i >> 2] ? sp[i] : -1e30f;
        int   iv[K_]; float wv[K_];
        for (int rsel = 0; rsel < K_; rsel++) {
            int best = 0; float bv = -1e31f;
            for (int i = 0; i < E_; i++)
                if (masked[i] > bv) { bv = masked[i]; best = i; }
            iv[rsel] = best; wv[rsel] = bv;
            masked[best] = -1e31f;
        }
        float mm = wv[0];
        float ssum = 0.f;
        #pragma unroll
        for (int rsel = 0; rsel < K_; rsel++) { wv[rsel] = expf(wv[rsel] - mm); ssum += wv[rsel]; }
        bool hit[D_] = {};
        #pragma unroll
        for (int rsel = 0; rsel < K_; rsel++) hit[iv[rsel] >> 2] = true;
        for (int d = 0; d < D_; d++)
            if (hit[d]) atomicAdd(&g_comm[d], 1.0f);
        #pragma unroll
        for (int rsel = 0; rsel < K_; rsel++) {
            int idx = t * K_ + rsel;
            g_sel_e[idx] = iv[rsel];
            g_sel_w[idx] = wv[rsel] / ssum;
            atomicAdd(&g_cnt[iv[rsel]], 1);
        }
    }
}

__global__ void offsets_kernel() {
    if (threadIdx.x == 0) {
        int s = 0;
        for (int e = 0; e < E_; e++) { g_off[e] = s; g_cur[e] = s; s += g_cnt[e]; }
    }
}

__global__ void scatter_kernel() {
    int i = blockIdx.x * 256 + threadIdx.x;
    if (i >= TK_) return;
    int e = g_sel_e[i];
    int pos = atomicAdd(&g_cur[e], 1);
    g_ltok[pos]  = i / K_;
    g_lslot[pos] = i;
    g_lw[pos]    = g_sel_w[i];
}

// ---------------- final combine + rmsnorm + aux -------------------------------
__global__ __launch_bounds__(256)
void final_kernel(float* __restrict__ out) {
    const int t = blockIdx.x;
    float v[4]; float ss = 0.f;
    #pragma unroll
    for (int i = 0; i < 4; i++) {
        int j = i * 256 + threadIdx.x;
        float s = g_h1[(size_t)t * H_ + j]
                + g_sdwn[(size_t)t * H_ + j]
                + g_sdwn[(size_t)(T_ + t) * H_ + j];
        #pragma unroll
        for (int k = 0; k < K_; k++)
            s += g_rdwn[(size_t)(t * K_ + k) * H_ + j];
        v[i] = s; ss += s * s;
    }
    ss = block_sum256(ss);
    float inv = rsqrtf(ss * (1.f / H_) + EPS_);
    #pragma unroll
    for (int i = 0; i < 4; i++) {
        int j = i * 256 + threadIdx.x;
        out[(size_t)t * H_ + j] = v[i] * inv;
    }
}

__global__ void aux_kernel(float* out, int out_size) {
    if (out_size <= T_ * H_) return;
    const float fTK = (float)TK_ + 1e-10f;
    float fi[E_], Pi[E_];
    float s1 = 0.f;
    for (int e = 0; e < E_; e++) {
        fi[e] = (float)g_cnt[e] / fTK;
        Pi[e] = g_Pi[e] / (float)T_;
        s1 += fi[e] * Pi[e];
    }
    float eb = fminf(s1 * 0.003f, 10.f);
    float dP[D_];
    float s2 = 0.f;
    for (int d = 0; d < D_; d++) {
        float df = (fi[4*d] + fi[4*d+1] + fi[4*d+2] + fi[4*d+3]) * 0.25f;
        dP[d]    = Pi[4*d] + Pi[4*d+1] + Pi[4*d+2] + Pi[4*d+3];
        s2 += df * dP[d];
    }
    float db = fminf(s2 * 0.05f, 10.f);
    float s3 = 0.f;
    for (int d = 0; d < D_; d++) {
        float fc = g_comm[d] / ((float)(T_ * KD_) + 1e-10f);
        s3 += fc * dP[d];
    }
    float cb = fminf(s3 * 0.02f, 10.f);
    out[T_ * H_] = eb + db + cb;
}

// ---------------- host driver -------------------------------------------------
extern "C" void kernel_launch(void* const* d_in, const int* in_sizes, int n_in,
                              void* d_out, int out_size) {
    const float* x     = (const float*)d_in[0];
    const float* Wqkv  = (const float*)d_in[1];
    const float* Wo    = (const float*)d_in[2];
    const float* Wgu_s = (const float*)d_in[3];
    const float* Wd_s  = (const float*)d_in[4];
    const float* Wr    = (const float*)d_in[5];
    const float* Wgu   = (const float*)d_in[6];
    const float* Wd    = (const float*)d_in[7];
    float* out = (float*)d_out;

    float *p_qkv, *p_attn, *p_tmp, *p_h1, *p_sgu, *p_sdwn, *p_rgu, *p_rdwn;
    cudaGetSymbolAddress((void**)&p_qkv,  g_qkv);
    cudaGetSymbolAddress((void**)&p_attn, g_attn);
    cudaGetSymbolAddress((void**)&p_tmp,  g_tmp);
    cudaGetSymbolAddress((void**)&p_h1,   g_h1);
    cudaGetSymbolAddress((void**)&p_sgu,  g_sgu);
    cudaGetSymbolAddress((void**)&p_sdwn, g_sdwn);
    cudaGetSymbolAddress((void**)&p_rgu,  g_rgu);
    cudaGetSymbolAddress((void**)&p_rdwn, g_rdwn);

    static bool init_done = false;
    static cudaStream_t s1;
    static cudaEvent_t evFork, evJoin;
    if (!init_done) {
        cudaFuncSetAttribute(mt_gemm<0,0,false>, cudaFuncAttributeMaxDynamicSharedMemorySize, (int)SMEM_G);
        cudaFuncSetAttribute(mt_gemm<2,0,false>, cudaFuncAttributeMaxDynamicSharedMemorySize, (int)SMEM_G);
        cudaFuncSetAttribute(mt_gemm<1,1,true>,  cudaFuncAttributeMaxDynamicSharedMemorySize, (int)SMEM_G);
        cudaFuncSetAttribute(mt_gemm<2,2,true>,  cudaFuncAttributeMaxDynamicSharedMemorySize, (int)SMEM_G);
        cudaStreamCreateWithFlags(&s1, cudaStreamNonBlocking);
        cudaEventCreateWithFlags(&evFork, cudaEventDisableTiming);
        cudaEventCreateWithFlags(&evJoin, cudaEventDisableTiming);
        init_done = true;
    }

    zero_small<<<1, 64>>>();

    // qkv = x @ Wqkv  (M=1024, N=3072, K=1024)
    mt_gemm<0,0,false><<<dim3(12, 16, 1), 256, SMEM_G>>>(
        x, H_, 0, Wqkv, 0, 3 * H_, H_, p_qkv, 0);

    // attention
    flash_attn<<<dim3(S_ / 64, NH_, B_), 256>>>();

    // Wo split-K=2 via batch strides (z offsets A by 512 cols, B by 512 rows)
    mt_gemm<0,0,false><<<dim3(4, 16, 2), 256, SMEM_G>>>(
        p_attn, H_, 512, Wo, (size_t)512 * H_, H_, 512, p_tmp, (size_t)T_ * H_);
    resid_rms3<<<T_, 256>>>(x, p_tmp, p_tmp + (size_t)T_ * H_, p_h1);

    // fork: shared experts on s1
    cudaEventRecord(evFork, 0);
    cudaStreamWaitEvent(s1, evFork, 0);
    mt_gemm<0,0,false><<<dim3(12, 16, 2), 256, SMEM_G, s1>>>(
        p_h1, H_, 0, Wgu_s, (size_t)H_ * 2 * I_, 2 * I_, H_, p_sgu, (size_t)T_ * 2 * I_);
    mt_gemm<2,0,false><<<dim3(4, 16, 2), 256, SMEM_G, s1>>>(
        p_sgu, 2 * I_, (size_t)T_ * 2 * I_, Wd_s, (size_t)I_ * H_, H_, I_, p_sdwn, (size_t)T_ * H_);
    cudaEventRecord(evJoin, s1);

    // routed chain on main stream
    routing_kernel<<<T_, 32>>>(Wr);
    offsets_kernel<<<1, 32>>>();
    scatter_kernel<<<(TK_ + 255) / 256, 256>>>();
    mt_gemm<1,1,true><<<dim3(12, 16, E_), 256, SMEM_G>>>(
        p_h1, H_, 0, Wgu, (size_t)H_ * 2 * I_, 2 * I_, H_, p_rgu, 0);
    mt_gemm<2,2,true><<<dim3(4, 16, E_), 256, SMEM_G>>>(
        p_rgu, 2 * I_, 0, Wd, (size_t)I_ * H_, H_, I_, p_rdwn, 0);

    // join and finish
    cudaStreamWaitEvent(0, evJoin, 0);
    final_kernel<<<T_, 256>>>(out);
    aux_kernel<<<1, 1>>>(out, out_size);
}

// round 14
// speedup vs baseline: 1.9630x; 1.4465x over previous
#include <cuda_runtime.h>
#include <cuda_bf16.h>
#include <math.h>
#include <stdint.h>

// ---------------- problem constants ----------------
#define B_   2
#define S_   512
#define T_   1024
#define H_   1024
#define NH_  16
#define HD_  64
#define E_   32
#define D_   8
#define K_   6
#define KD_  3
#define I_   1536
#define EPS_ 1e-5f
#define TK_  (T_*K_)

// ---------------- device scratch ----------------
__device__ float g_qkv [T_*3*H_];
__device__ float g_attn[T_*H_];
__device__ float g_tmp [2*T_*H_];
__device__ float g_h1  [T_*H_];
__device__ float g_sgu [2*T_*2*I_];
__device__ float g_sdwn[2*T_*H_];
__device__ float g_rgu [TK_*2*I_];
__device__ float g_rdwn[TK_*H_];

__device__ float g_Pi  [E_];
__device__ float g_comm[D_];
__device__ int   g_cnt [E_];
__device__ int   g_off [E_];
__device__ int   g_cur [E_];
__device__ int   g_sel_e[TK_];
__device__ float g_sel_w[TK_];
__device__ int   g_ltok [TK_];
__device__ int   g_lslot[TK_];
__device__ float g_lw   [TK_];

__device__ __forceinline__ float silu1(float g) { return g / (1.f + expf(-g)); }

__device__ __forceinline__ float block_sum256(float v) {
    __shared__ float red[8];
    __shared__ float tot;
    #pragma unroll
    for (int o = 16; o; o >>= 1) v += __shfl_xor_sync(0xffffffffu, v, o);
    if ((threadIdx.x & 31) == 0) red[threadIdx.x >> 5] = v;
    __syncthreads();
    if (threadIdx.x < 8) {
        float s = red[threadIdx.x];
        #pragma unroll
        for (int o = 4; o; o >>= 1) s += __shfl_xor_sync(0xffu, s, o);
        if (threadIdx.x == 0) tot = s;
    }
    __syncthreads();
    return tot;
}

// ---------------- mma/ldmatrix primitives -----------------------------------
__device__ __forceinline__ uint32_t smem_u32(const void* p) {
    return (uint32_t)__cvta_generic_to_shared(p);
}
__device__ __forceinline__ void ldm_x4(uint32_t r[4], uint32_t addr) {
    asm volatile("ldmatrix.sync.aligned.m8n8.x4.shared.b16 {%0,%1,%2,%3},[%4];"
        : "=r"(r[0]), "=r"(r[1]), "=r"(r[2]), "=r"(r[3]) : "r"(addr));
}
__device__ __forceinline__ void ldm_x4t(uint32_t r[4], uint32_t addr) {
    asm volatile("ldmatrix.sync.aligned.m8n8.x4.trans.shared.b16 {%0,%1,%2,%3},[%4];"
        : "=r"(r[0]), "=r"(r[1]), "=r"(r[2]), "=r"(r[3]) : "r"(addr));
}
__device__ __forceinline__ void mma_bf16(float c[4], const uint32_t a[4],
                                         uint32_t b0, uint32_t b1) {
    asm volatile(
        "mma.sync.aligned.m16n8k16.row.col.f32.bf16.bf16.f32 "
        "{%0,%1,%2,%3},{%4,%5,%6,%7},{%8,%9},{%0,%1,%2,%3};"
        : "+f"(c[0]), "+f"(c[1]), "+f"(c[2]), "+f"(c[3])
        : "r"(a[0]), "r"(a[1]), "r"(a[2]), "r"(a[3]), "r"(b0), "r"(b1));
}

__device__ __forceinline__ void split2(float2 v, __nv_bfloat162& h, __nv_bfloat162& l) {
    h = __float22bfloat162_rn(v);
    float2 r = make_float2(v.x - __bfloat162float(h.x), v.y - __bfloat162float(h.y));
    l = __float22bfloat162_rn(r);
}
__device__ __forceinline__ void stage8(__nv_bfloat16* dh, __nv_bfloat16* dl,
                                       float4 f0, float4 f1) {
    __nv_bfloat162 h[4], l[4];
    split2(make_float2(f0.x, f0.y), h[0], l[0]);
    split2(make_float2(f0.z, f0.w), h[1], l[1]);
    split2(make_float2(f1.x, f1.y), h[2], l[2]);
    split2(make_float2(f1.z, f1.w), h[3], l[3]);
    *(uint4*)dh = *(uint4*)h;
    *(uint4*)dl = *(uint4*)l;
}

// ---------------- BK=32 smem geometry (dynamic smem) -------------------------
#define APX 40          // A pitch in halfs (80B rows -> conflict-free ldmatrix)
#define BPX 136         // B pitch in halfs (272B rows -> conflict-free trans)
#define AH_SZ (2*64*APX)       // per-field elems, 2 buffers
#define BH_SZ (2*32*BPX)
#define SMEM_BYTES ((2*AH_SZ + 2*BH_SZ) * 2)   // 55296 B

// one k16 substep (ks in {0,1}); warp layout wm:{0,1} x wn:{0..3}, NF=4
__device__ __forceinline__ void stepX(
    const __nv_bfloat16* Ah, const __nv_bfloat16* Al,
    const __nv_bfloat16* Bh, const __nv_bfloat16* Bl,
    int ks, int wm, int wn, int lane, float (*acc)[4])
{
    uint32_t ah[2][4], al[2][4];
    const int arow = lane & 15, acol = (lane >> 4) * 8;
    #pragma unroll
    for (int mf = 0; mf < 2; mf++) {
        int off = (wm * 32 + mf * 16 + arow) * APX + ks * 16 + acol;
        ldm_x4(ah[mf], smem_u32(Ah + off));
        ldm_x4(al[mf], smem_u32(Al + off));
    }
    const int bkr = lane & 15;
    const int bnl = (lane >> 4) * 8;
    #pragma unroll
    for (int nf2 = 0; nf2 < 2; nf2++) {
        int off = (ks * 16 + bkr) * BPX + wn * 32 + nf2 * 16 + bnl;
        uint32_t bh[4], bl4[4];
        ldm_x4t(bh,  smem_u32(Bh + off));
        ldm_x4t(bl4, smem_u32(Bl + off));
        #pragma unroll
        for (int mf = 0; mf < 2; mf++) {
            float* c0 = acc[mf * 4 + nf2 * 2 + 0];
            float* c1 = acc[mf * 4 + nf2 * 2 + 1];
            mma_bf16(c0, ah[mf], bh[0],  bh[1]);
            mma_bf16(c0, ah[mf], bl4[0], bl4[1]);
            mma_bf16(c0, al[mf], bh[0],  bh[1]);
            mma_bf16(c1, ah[mf], bh[2],  bh[3]);
            mma_bf16(c1, ah[mf], bl4[2], bl4[3]);
            mma_bf16(c1, al[mf], bh[2],  bh[3]);
        }
    }
}

#define GEMM_PREAMBLE \
    extern __shared__ __nv_bfloat16 dsm[]; \
    __nv_bfloat16* sAh = dsm; \
    __nv_bfloat16* sAl = dsm + AH_SZ; \
    __nv_bfloat16* sBh = dsm + 2 * AH_SZ; \
    __nv_bfloat16* sBl = dsm + 2 * AH_SZ + BH_SZ; \
    const int tid = threadIdx.x, lane = tid & 31, wid = tid >> 5; \
    const int wm = wid & 1, wn = wid >> 1; \
    const int ar = tid >> 2, akc = (tid & 3) * 8; \
    const int bk = tid >> 4, bnc = (tid & 15) * 8; \
    float acc[8][4]; \
    _Pragma("unroll") for (int i = 0; i < 8; i++) \
        _Pragma("unroll") for (int j = 0; j < 4; j++) acc[i][j] = 0.f;

#define A_AT(buf, r, c) (sAh + (buf) * (64 * APX) + (r) * APX + (c))
#define AL_AT(buf, r, c) (sAl + (buf) * (64 * APX) + (r) * APX + (c))
#define B_AT(buf, r, c) (sBh + (buf) * (32 * BPX) + (r) * BPX + (c))
#define BL_AT(buf, r, c) (sBl + (buf) * (32 * BPX) + (r) * BPX + (c))

#define STORE_A(buf) \
    stage8(A_AT(buf, ar, akc), AL_AT(buf, ar, akc), fa0, fa1);
#define STORE_B1(buf) \
    stage8(B_AT(buf, bk, bnc), BL_AT(buf, bk, bnc), fb0, fb1);
#define STORE_B2(buf) \
    stage8(B_AT(buf, bk + 16, bnc), BL_AT(buf, bk + 16, bnc), fb0, fb1);

#define LOAD_B1(k0) \
    fb0 = *(const float4*)(Bg + (size_t)(k0) * N); \
    fb1 = *(const float4*)(Bg + (size_t)(k0) * N + 4);
#define LOAD_B2(k0) \
    fb0 = *(const float4*)(Bg + (size_t)((k0) + 16) * N); \
    fb1 = *(const float4*)(Bg + (size_t)((k0) + 16) * N + 4);

#define MAINLOOP(LOAD_A) \
    __syncthreads(); \
    const int nK = Kd >> 5; \
    int buf = 0; \
    for (int kt = 0; kt < nK; kt++) { \
        const bool nxt = (kt + 1) < nK; \
        const int k0 = (kt + 1) << 5; \
        if (nxt) { LOAD_A(k0); LOAD_B1(k0); } \
        stepX(A_AT(buf,0,0), AL_AT(buf,0,0), B_AT(buf,0,0), BL_AT(buf,0,0), 0, wm, wn, lane, acc); \
        if (nxt) { int nb = buf ^ 1; STORE_A(nb); STORE_B1(nb); LOAD_B2(k0); } \
        stepX(A_AT(buf,0,0), AL_AT(buf,0,0), B_AT(buf,0,0), BL_AT(buf,0,0), 1, wm, wn, lane, acc); \
        if (nxt) { int nb = buf ^ 1; STORE_B2(nb); } \
        __syncthreads(); \
        buf ^= 1; \
    }

#define PROLOGUE(LOAD_A) \
    float4 fa0, fa1, fb0, fb1; \
    LOAD_A(0) STORE_A(0) \
    LOAD_B1(0) STORE_B1(0) \
    LOAD_B2(0) STORE_B2(0)

// ============================================================================
// Batched dense GEMM: C[z] = A @ B[z]. BM=64, BN=128, BK=32.
// ============================================================================
#define LOADA_PLAIN(k0) \
    fa0 = *(const float4*)(Ag + (k0)); fa1 = *(const float4*)(Ag + (k0) + 4);

__global__ __launch_bounds__(256, 3)
void mma_d64_batch(const float* __restrict__ A, const float* __restrict__ Bw,
                   float* __restrict__ C, int Kd, int N,
                   size_t bStride, size_t cStride)
{
    GEMM_PREAMBLE
    const int m0 = blockIdx.y * 64, n0 = blockIdx.x * 128;
    const float* Bz = Bw + (size_t)blockIdx.z * bStride;
    float* Cz = C + (size_t)blockIdx.z * cStride;
    const float* Ag = A + (size_t)(m0 + ar) * Kd + akc;
    const float* Bg = Bz + (size_t)bk * N + n0 + bnc;

    PROLOGUE(LOADA_PLAIN)
    MAINLOOP(LOADA_PLAIN)

    #pragma unroll
    for (int mf = 0; mf < 2; mf++)
        #pragma unroll
        for (int nf = 0; nf < 4; nf++) {
            float* c = acc[mf * 4 + nf];
            int r0  = m0 + wm * 32 + mf * 16 + (lane >> 2);
            int col = n0 + wn * 32 + nf * 8 + (lane & 3) * 2;
            float* p0 = Cz + (size_t)r0 * N + col;
            float* p1 = Cz + (size_t)(r0 + 8) * N + col;
            p0[0] = c[0]; p0[1] = c[1]; p1[0] = c[2]; p1[1] = c[3];
        }
}

// ============================================================================
// Split-K dense GEMM (Wo): z halves K, partials to C + z*T*H.
// ============================================================================
__global__ __launch_bounds__(256, 3)
void mma_d64_splitk(const float* __restrict__ A, const float* __restrict__ Bw,
                    float* __restrict__ C, int KdFull, int N)
{
    GEMM_PREAMBLE
    const int m0 = blockIdx.y * 64, n0 = blockIdx.x * 128;
    const int Kd = KdFull >> 1;
    const int kOff = blockIdx.z * Kd;
    float* Cz = C + (size_t)blockIdx.z * T_ * H_;
    const float* Ag = A + (size_t)(m0 + ar) * KdFull + kOff + akc;
    const float* Bg = Bw + (size_t)(kOff + bk) * N + n0 + bnc;

    PROLOGUE(LOADA_PLAIN)
    MAINLOOP(LOADA_PLAIN)

    #pragma unroll
    for (int mf = 0; mf < 2; mf++)
        #pragma unroll
        for (int nf = 0; nf < 4; nf++) {
            float* c = acc[mf * 4 + nf];
            int r0  = m0 + wm * 32 + mf * 16 + (lane >> 2);
            int col = n0 + wn * 32 + nf * 8 + (lane & 3) * 2;
            float* p0 = Cz + (size_t)r0 * N + col;
            float* p1 = Cz + (size_t)(r0 + 8) * N + col;
            p0[0] = c[0]; p0[1] = c[1]; p1[0] = c[2]; p1[1] = c[3];
        }
}

// ============================================================================
// Shared-expert down GEMM (fused SwiGLU A), batched over z=e.
// ============================================================================
#define LOADA_SWI(k0) { \
    float4 gg0 = *(const float4*)(Gg + (k0)), gg1 = *(const float4*)(Gg + (k0) + 4); \
    float4 uu0 = *(const float4*)(Gg + (k0) + I_), uu1 = *(const float4*)(Gg + (k0) + I_ + 4); \
    fa0 = make_float4(silu1(gg0.x)*uu0.x, silu1(gg0.y)*uu0.y, silu1(gg0.z)*uu0.z, silu1(gg0.w)*uu0.w); \
    fa1 = make_float4(silu1(gg1.x)*uu1.x, silu1(gg1.y)*uu1.y, silu1(gg1.z)*uu1.z, silu1(gg1.w)*uu1.w); }

__global__ __launch_bounds__(256, 3)
void mma_shared_down(const float* __restrict__ Wd_s)
{
    GEMM_PREAMBLE
    const int N = H_, Kd = I_;
    const int m0 = blockIdx.y * 64, n0 = blockIdx.x * 128;
    const int e = blockIdx.z;
    const float* Gg = g_sgu + (size_t)e * T_ * 2 * I_ + (size_t)(m0 + ar) * (2 * I_) + akc;
    const float* Bg = Wd_s + (size_t)e * I_ * H_ + (size_t)bk * N + n0 + bnc;
    float* Cz = g_sdwn + (size_t)e * T_ * H_;

    PROLOGUE(LOADA_SWI)
    MAINLOOP(LOADA_SWI)

    #pragma unroll
    for (int mf = 0; mf < 2; mf++)
        #pragma unroll
        for (int nf = 0; nf < 4; nf++) {
            float* c = acc[mf * 4 + nf];
            int r0  = m0 + wm * 32 + mf * 16 + (lane >> 2);
            int col = n0 + wn * 32 + nf * 8 + (lane & 3) * 2;
            float* p0 = Cz + (size_t)r0 * N + col;
            float* p1 = Cz + (size_t)(r0 + 8) * N + col;
            p0[0] = c[0]; p0[1] = c[1]; p1[0] = c[2]; p1[1] = c[3];
        }
}

// ============================================================================
// Routed up GEMM: gathered A rows from g_h1. grid=(2I/128, T/64, E).
// ============================================================================
#define LOADA_GATH(k0) \
    fa0 = (tok >= 0) ? *(const float4*)(Ag + (k0)) : make_float4(0.f,0.f,0.f,0.f); \
    fa1 = (tok >= 0) ? *(const float4*)(Ag + (k0) + 4) : make_float4(0.f,0.f,0.f,0.f);

__global__ __launch_bounds__(256, 3)
void mma_up_routed(const float* __restrict__ Wgu)
{
    const int e = blockIdx.z;
    const int cnt = g_cnt[e];
    const int m0 = blockIdx.y * 64;
    if (m0 >= cnt) return;
    GEMM_PREAMBLE
    const int off = g_off[e];
    const int n0 = blockIdx.x * 128;
    const int N = 2 * I_, Kd = H_;
    const int tok = (m0 + ar < cnt) ? g_ltok[off + m0 + ar] : -1;
    const float* Ag = (tok >= 0) ? (g_h1 + (size_t)tok * H_ + akc) : g_h1;
    const float* Bg = Wgu + (size_t)e * H_ * 2 * I_ + (size_t)bk * N + n0 + bnc;

    PROLOGUE(LOADA_GATH)
    MAINLOOP(LOADA_GATH)

    #pragma unroll
    for (int mf = 0; mf < 2; mf++)
        #pragma unroll
        for (int nf = 0; nf < 4; nf++) {
            float* c = acc[mf * 4 + nf];
            int lr0 = m0 + wm * 32 + mf * 16 + (lane >> 2);
            int col = n0 + wn * 32 + nf * 8 + (lane & 3) * 2;
            if (lr0 < cnt) {
                float* p = g_rgu + (size_t)(off + lr0) * N + col;
                p[0] = c[0]; p[1] = c[1];
            }
            if (lr0 + 8 < cnt) {
                float* p = g_rgu + (size_t)(off + lr0 + 8) * N + col;
                p[0] = c[2]; p[1] = c[3];
            }
        }
}

// ============================================================================
// Routed down GEMM: fused SwiGLU A from g_rgu, weighted scatter epilogue.
// ============================================================================
#define LOADA_SWIR(k0) \
    if (aok) { \
        float4 gg0 = *(const float4*)(Ag + (k0)), gg1 = *(const float4*)(Ag + (k0) + 4); \
        float4 uu0 = *(const float4*)(Ag + (k0) + I_), uu1 = *(const float4*)(Ag + (k0) + I_ + 4); \
        fa0 = make_float4(silu1(gg0.x)*uu0.x, silu1(gg0.y)*uu0.y, silu1(gg0.z)*uu0.z, silu1(gg0.w)*uu0.w); \
        fa1 = make_float4(silu1(gg1.x)*uu1.x, silu1(gg1.y)*uu1.y, silu1(gg1.z)*uu1.z, silu1(gg1.w)*uu1.w); \
    } else { fa0 = fa1 = make_float4(0.f,0.f,0.f,0.f); }

__global__ __launch_bounds__(256, 3)
void mma_down_routed(const float* __restrict__ Wd)
{
    const int e = blockIdx.z;
    const int cnt = g_cnt[e];
    const int m0 = blockIdx.y * 64;
    if (m0 >= cnt) return;
    GEMM_PREAMBLE
    const int off = g_off[e];
    const int n0 = blockIdx.x * 128;
    const int N = H_, Kd = I_;
    const bool aok = (m0 + ar) < cnt;
    const float* Ag = g_rgu + (size_t)(off + (aok ? m0 + ar : 0)) * (2 * I_) + akc;
    const float* Bg = Wd + (size_t)e * I_ * H_ + (size_t)bk * N + n0 + bnc;

    PROLOGUE(LOADA_SWIR)
    MAINLOOP(LOADA_SWIR)

    #pragma unroll
    for (int mf = 0; mf < 2; mf++)
        #pragma unroll
        for (int nf = 0; nf < 4; nf++) {
            float* c = acc[mf * 4 + nf];
            int lr0 = m0 + wm * 32 + mf * 16 + (lane >> 2);
            int col = n0 + wn * 32 + nf * 8 + (lane & 3) * 2;
            if (lr0 < cnt) {
                int slot = g_lslot[off + lr0];
                float w  = g_lw[off + lr0];
                float* p = g_rdwn + (size_t)slot * H_ + col;
                p[0] = w * c[0]; p[1] = w * c[1];
            }
            if (lr0 + 8 < cnt) {
                int slot = g_lslot[off + lr0 + 8];
                float w  = g_lw[off + lr0 + 8];
                float* p = g_rdwn + (size_t)slot * H_ + col;
                p[0] = w * c[2]; p[1] = w * c[3];
            }
        }
}

// ---------------- flash attention (fp32, validated) --------------------------
__global__ __launch_bounds__(256)
void flash_attn() {
    __shared__ float Qs[64][68];
    __shared__ float Ks[32][68];
    __shared__ float Vs[32][68];
    __shared__ float Ps[64][36];
    const int q0 = blockIdx.x * 64;
    const int h  = blockIdx.y;
    const int b  = blockIdx.z;
    const int tid = threadIdx.x;
    const size_t rs = 3 * H_;
    const float* qb = g_qkv + (size_t)b * S_ * rs + (size_t)h * HD_;
    const float* kb = qb + H_;
    const float* vb = qb + 2 * H_;
    const float scale = 0.125f;
    for (int i = tid; i < 64 * 64; i += 256) {
        int r = i >> 6, d = i & 63;
        Qs[r][d] = qb[(size_t)(q0 + r) * rs + d] * scale;
    }
    const int r  = tid >> 2;
    const int c4 = tid & 3;
    float m_i = -1e30f, l_i = 0.f;
    float acc[16];
    #pragma unroll
    for (int i = 0; i < 16; i++) acc[i] = 0.f;
    __syncthreads();
    for (int kt = 0; kt < S_; kt += 32) {
        for (int i = tid; i < 32 * 64; i += 256) {
            int rr = i >> 6, d = i & 63;
            Ks[rr][d] = kb[(size_t)(kt + rr) * rs + d];
            Vs[rr][d] = vb[(size_t)(kt + rr) * rs + d];
        }
        __syncthreads();
        float sc[8];
        float mx = -1e30f;
        const float4* qrow = (const float4*)&Qs[r][0];
        #pragma unroll
        for (int jj = 0; jj < 8; jj++) {
            int j = c4 * 8 + jj;
            const float4* krow = (const float4*)&Ks[j][0];
            float sv = 0.f;
            #pragma unroll
            for (int dv = 0; dv < 16; dv++) {
                float4 a = qrow[dv], bq = krow[dv];
                sv += a.x * bq.x + a.y * bq.y + a.z * bq.z + a.w * bq.w;
            }
            sc[jj] = sv; mx = fmaxf(mx, sv);
        }
        mx = fmaxf(mx, __shfl_xor_sync(0xffffffffu, mx, 1));
        mx = fmaxf(mx, __shfl_xor_sync(0xffffffffu, mx, 2));
        float m_new = fmaxf(m_i, mx);
        float alpha = expf(m_i - m_new);
        float psum = 0.f;
        #pragma unroll
        for (int jj = 0; jj < 8; jj++) {
            float p = expf(sc[jj] - m_new);
            Ps[r][c4 * 8 + jj] = p;
            psum += p;
        }
        psum += __shfl_xor_sync(0xffffffffu, psum, 1);
        psum += __shfl_xor_sync(0xffffffffu, psum, 2);
        l_i = l_i * alpha + psum;
        m_i = m_new;
        #pragma unroll
        for (int i = 0; i < 16; i++) acc[i] *= alpha;
        __syncwarp();
        #pragma unroll
        for (int i = 0; i < 16; i++) {
            int d = c4 * 16 + i;
            float s = 0.f;
            #pragma unroll 8
            for (int j = 0; j < 32; j++) s += Ps[r][j] * Vs[j][d];
            acc[i] += s;
        }
        __syncthreads();
    }
    float inv = 1.f / l_i;
    float* ob = g_attn + (size_t)((b * S_ + q0 + r)) * H_ + (size_t)h * HD_;
    #pragma unroll
    for (int i = 0; i < 16; i++) ob[c4 * 16 + i] = acc[i] * inv;
}

// ---------------- residual + rmsnorm over 3-way sum --------------------------
__global__ __launch_bounds__(256)
void resid_rms3(const float* __restrict__ a, const float* __restrict__ b0,
                const float* __restrict__ b1, float* __restrict__ o) {
    const int t = blockIdx.x;
    float v[4]; float ss = 0.f;
    #pragma unroll
    for (int i = 0; i < 4; i++) {
        int j = i * 256 + threadIdx.x;
        float s = a[(size_t)t * H_ + j] + b0[(size_t)t * H_ + j] + b1[(size_t)t * H_ + j];
        v[i] = s; ss += s * s;
    }
    ss = block_sum256(ss);
    float inv = rsqrtf(ss * (1.f / H_) + EPS_);
    #pragma unroll
    for (int i = 0; i < 4; i++) {
        int j = i * 256 + threadIdx.x;
        o[(size_t)t * H_ + j] = v[i] * inv;
    }
}

// ---------------- routing ----------------------------------------------------
__global__ void zero_small() {
    int i = threadIdx.x;
    if (i < E_) { g_Pi[i] = 0.f; g_cnt[i] = 0; }
    if (i < D_)   g_comm[i] = 0.f;
}

__global__ void routing_kernel(const float* __restrict__ Wr) {
    const int t = blockIdx.x;
    const int e = threadIdx.x;
    const float* xr = g_h1 + (size_t)t * H_;
    float logit = 0.f;
    for (int j = 0; j < H_; j++) logit += xr[j] * Wr[(size_t)j * E_ + e];
    float m = logit;
    #pragma unroll
    for (int o = 16; o; o >>= 1) m = fmaxf(m, __shfl_xor_sync(0xffffffffu, m, o));
    float ex = expf(logit - m);
    float s = ex;
    #pragma unroll
    for (int o = 16; o; o >>= 1) s += __shfl_xor_sync(0xffffffffu, s, o);
    float prob = ex / s;
    atomicAdd(&g_Pi[e], prob);
    __shared__ float sp[E_];
    sp[e] = prob;
    __syncwarp();
    if (e == 0) {
        float ds[D_];
        #pragma unroll
        for (int d = 0; d < D_; d++)
            ds[d] = sp[4*d] + sp[4*d+1] + sp[4*d+2] + sp[4*d+3];
        bool dsel[D_] = {};
        for (int rsel = 0; rsel < KD_; rsel++) {
            int best = -1; float bv = -1e30f;
            for (int d = 0; d < D_; d++)
                if (!dsel[d] && ds[d] > bv) { bv = ds[d]; best = d; }
            dsel[best] = true;
        }
        float masked[E_];
        #pragma unroll
        for (int i = 0; i < E_; i++)
            masked[i] = dsel[i >> 2] ? sp[i] : -1e30f;
        int   iv[K_]; float wv[K_];
        for (int rsel = 0; rsel < K_; rsel++) {
            int best = 0; float bv = -1e31f;
            for (int i = 0; i < E_; i++)
                if (masked[i] > bv) { bv = masked[i]; best = i; }
            iv[rsel] = best; wv[rsel] = bv;
            masked[best] = -1e31f;
        }
        float mm = wv[0];
        float ssum = 0.f;
        #pragma unroll
        for (int rsel = 0; rsel < K_; rsel++) { wv[rsel] = expf(wv[rsel] - mm); ssum += wv[rsel]; }
        bool hit[D_] = {};
        #pragma unroll
        for (int rsel = 0; rsel < K_; rsel++) hit[iv[rsel] >> 2] = true;
        for (int d = 0; d < D_; d++)
            if (hit[d]) atomicAdd(&g_comm[d], 1.0f);
        #pragma unroll
        for (int rsel = 0; rsel < K_; rsel++) {
            int idx = t * K_ + rsel;
            g_sel_e[idx] = iv[rsel];
            g_sel_w[idx] = wv[rsel] / ssum;
            atomicAdd(&g_cnt[iv[rsel]], 1);
        }
    }
}

__global__ void offsets_kernel() {
    if (threadIdx.x == 0) {
        int s = 0;
        for (int e = 0; e < E_; e++) { g_off[e] = s; g_cur[e] = s; s += g_cnt[e]; }
    }
}

__global__ void scatter_kernel() {
    int i = blockIdx.x * 256 + threadIdx.x;
    if (i >= TK_) return;
    int e = g_sel_e[i];
    int pos = atomicAdd(&g_cur[e], 1);
    g_ltok[pos]  = i / K_;
    g_lslot[pos] = i;
    g_lw[pos]    = g_sel_w[i];
}

// ---------------- final combine + rmsnorm + aux -------------------------------
__global__ __launch_bounds__(256)
void final_kernel(float* __restrict__ out) {
    const int t = blockIdx.x;
    float v[4]; float ss = 0.f;
    #pragma unroll
    for (int i = 0; i < 4; i++) {
        int j = i * 256 + threadIdx.x;
        float s = g_h1[(size_t)t * H_ + j]
                + g_sdwn[(size_t)t * H_ + j]
                + g_sdwn[(size_t)(T_ + t) * H_ + j];
        #pragma unroll
        for (int k = 0; k < K_; k++)
            s += g_rdwn[(size_t)(t * K_ + k) * H_ + j];
        v[i] = s; ss += s * s;
    }
    ss = block_sum256(ss);
    float inv = rsqrtf(ss * (1.f / H_) + EPS_);
    #pragma unroll
    for (int i = 0; i < 4; i++) {
        int j = i * 256 + threadIdx.x;
        out[(size_t)t * H_ + j] = v[i] * inv;
    }
}

__global__ void aux_kernel(float* out, int out_size) {
    if (out_size <= T_ * H_) return;
    const float fTK = (float)TK_ + 1e-10f;
    float fi[E_], Pi[E_];
    float s1 = 0.f;
    for (int e = 0; e < E_; e++) {
        fi[e] = (float)g_cnt[e] / fTK;
        Pi[e] = g_Pi[e] / (float)T_;
        s1 += fi[e] * Pi[e];
    }
    float eb = fminf(s1 * 0.003f, 10.f);
    float dP[D_];
    float s2 = 0.f;
    for (int d = 0; d < D_; d++) {
        float df = (fi[4*d] + fi[4*d+1] + fi[4*d+2] + fi[4*d+3]) * 0.25f;
        dP[d]    = Pi[4*d] + Pi[4*d+1] + Pi[4*d+2] + Pi[4*d+3];
        s2 += df * dP[d];
    }
    float db = fminf(s2 * 0.05f, 10.f);
    float s3 = 0.f;
    for (int d = 0; d < D_; d++) {
        float fc = g_comm[d] / ((float)(T_ * KD_) + 1e-10f);
        s3 += fc * dP[d];
    }
    float cb = fminf(s3 * 0.02f, 10.f);
    out[T_ * H_] = eb + db + cb;
}

// ---------------- host driver -------------------------------------------------
extern "C" void kernel_launch(void* const* d_in, const int* in_sizes, int n_in,
                              void* d_out, int out_size) {
    const float* x     = (const float*)d_in[0];
    const float* Wqkv  = (const float*)d_in[1];
    const float* Wo    = (const float*)d_in[2];
    const float* Wgu_s = (const float*)d_in[3];
    const float* Wd_s  = (const float*)d_in[4];
    const float* Wr    = (const float*)d_in[5];
    const float* Wgu   = (const float*)d_in[6];
    const float* Wd    = (const float*)d_in[7];
    float* out = (float*)d_out;

    float *p_qkv, *p_attn, *p_tmp, *p_h1, *p_sgu;
    cudaGetSymbolAddress((void**)&p_qkv,  g_qkv);
    cudaGetSymbolAddress((void**)&p_attn, g_attn);
    cudaGetSymbolAddress((void**)&p_tmp,  g_tmp);
    cudaGetSymbolAddress((void**)&p_h1,   g_h1);
    cudaGetSymbolAddress((void**)&p_sgu,  g_sgu);

    static bool init_done = false;
    static cudaStream_t s1;
    static cudaEvent_t evFork, evJoin;
    if (!init_done) {
        cudaFuncSetAttribute(mma_d64_batch,   cudaFuncAttributeMaxDynamicSharedMemorySize, SMEM_BYTES);
        cudaFuncSetAttribute(mma_d64_splitk,  cudaFuncAttributeMaxDynamicSharedMemorySize, SMEM_BYTES);
        cudaFuncSetAttribute(mma_shared_down, cudaFuncAttributeMaxDynamicSharedMemorySize, SMEM_BYTES);
        cudaFuncSetAttribute(mma_up_routed,   cudaFuncAttributeMaxDynamicSharedMemorySize, SMEM_BYTES);
        cudaFuncSetAttribute(mma_down_routed, cudaFuncAttributeMaxDynamicSharedMemorySize, SMEM_BYTES);
        cudaStreamCreateWithFlags(&s1, cudaStreamNonBlocking);
        cudaEventCreateWithFlags(&evFork, cudaEventDisableTiming);
        cudaEventCreateWithFlags(&evJoin, cudaEventDisableTiming);
        init_done = true;
    }

    zero_small<<<1, 64>>>();

    // qkv = x @ Wqkv
    mma_d64_batch<<<dim3(3 * H_ / 128, T_ / 64, 1), 256, SMEM_BYTES>>>(
        x, Wqkv, p_qkv, H_, 3 * H_, 0, 0);

    // attention
    flash_attn<<<dim3(S_ / 64, NH_, B_), 256>>>();

    // Wo split-K=2 ; h1 = rmsnorm(x + tmp0 + tmp1)
    mma_d64_splitk<<<dim3(H_ / 128, T_ / 64, 2), 256, SMEM_BYTES>>>(
        p_attn, Wo, p_tmp, H_, H_);
    resid_rms3<<<T_, 256>>>(x, p_tmp, p_tmp + (size_t)T_ * H_, p_h1);

    // fork: shared-expert chain on s1, routed chain on main stream
    cudaEventRecord(evFork, 0);
    cudaStreamWaitEvent(s1, evFork, 0);

    mma_d64_batch<<<dim3(2 * I_ / 128, T_ / 64, 2), 256, SMEM_BYTES, s1>>>(
        p_h1, Wgu_s, p_sgu, H_, 2 * I_,
        (size_t)H_ * 2 * I_, (size_t)T_ * 2 * I_);
    mma_shared_down<<<dim3(H_ / 128, T_ / 64, 2), 256, SMEM_BYTES, s1>>>(Wd_s);
    cudaEventRecord(evJoin, s1);

    routing_kernel<<<T_, 32>>>(Wr);
    offsets_kernel<<<1, 32>>>();
    scatter_kernel<<<(TK_ + 255) / 256, 256>>>();
    mma_up_routed<<<dim3(2 * I_ / 128, T_ / 64, E_), 256, SMEM_BYTES>>>(Wgu);
    mma_down_routed<<<dim3(H_ / 128, T_ / 64, E_), 256, SMEM_BYTES>>>(Wd);

    // join and finish
    cudaStreamWaitEvent(0, evJoin, 0);
    final_kernel<<<T_, 256>>>(out);
    aux_kernel<<<1, 1>>>(out, out_size);
}

// round 15
// speedup vs baseline: 2.3085x; 1.1760x over previous
#include <cuda_runtime.h>
#include <cuda_fp16.h>
#include <math.h>
#include <stdint.h>

// ---------------- problem constants ----------------
#define B_   2
#define S_   512
#define T_   1024
#define H_   1024
#define NH_  16
#define HD_  64
#define E_   32
#define D_   8
#define K_   6
#define KD_  3
#define I_   1536
#define EPS_ 1e-5f
#define TK_  (T_*K_)

// ---------------- device scratch ----------------
__device__ float g_qkv [T_*3*H_];
__device__ float g_attn[T_*H_];
__device__ float g_tmp [2*T_*H_];
__device__ float g_h1  [T_*H_];
__device__ float g_sgu [2*T_*2*I_];
__device__ float g_sdwn[2*T_*H_];
__device__ float g_rgu [TK_*2*I_];
__device__ float g_rdwn[TK_*H_];

__device__ float g_Pi  [E_];
__device__ float g_comm[D_];
__device__ int   g_cnt [E_];
__device__ int   g_off [E_];
__device__ int   g_cur [E_];
__device__ int   g_sel_e[TK_];
__device__ float g_sel_w[TK_];
__device__ int   g_ltok [TK_];
__device__ int   g_lslot[TK_];
__device__ float g_lw   [TK_];

__device__ __forceinline__ float silu1(float g) { return g / (1.f + expf(-g)); }

__device__ __forceinline__ float block_sum256(float v) {
    __shared__ float red[8];
    __shared__ float tot;
    #pragma unroll
    for (int o = 16; o; o >>= 1) v += __shfl_xor_sync(0xffffffffu, v, o);
    if ((threadIdx.x & 31) == 0) red[threadIdx.x >> 5] = v;
    __syncthreads();
    if (threadIdx.x < 8) {
        float s = red[threadIdx.x];
        #pragma unroll
        for (int o = 4; o; o >>= 1) s += __shfl_xor_sync(0xffu, s, o);
        if (threadIdx.x == 0) tot = s;
    }
    __syncthreads();
    return tot;
}

// ---------------- mma/ldmatrix primitives -----------------------------------
__device__ __forceinline__ uint32_t smem_u32(const void* p) {
    return (uint32_t)__cvta_generic_to_shared(p);
}
__device__ __forceinline__ void ldm_x4(uint32_t r[4], uint32_t addr) {
    asm volatile("ldmatrix.sync.aligned.m8n8.x4.shared.b16 {%0,%1,%2,%3},[%4];"
        : "=r"(r[0]), "=r"(r[1]), "=r"(r[2]), "=r"(r[3]) : "r"(addr));
}
__device__ __forceinline__ void ldm_x4t(uint32_t r[4], uint32_t addr) {
    asm volatile("ldmatrix.sync.aligned.m8n8.x4.trans.shared.b16 {%0,%1,%2,%3},[%4];"
        : "=r"(r[0]), "=r"(r[1]), "=r"(r[2]), "=r"(r[3]) : "r"(addr));
}
__device__ __forceinline__ void mma_f16(float c[4], const uint32_t a[4],
                                        uint32_t b0, uint32_t b1) {
    asm volatile(
        "mma.sync.aligned.m16n8k16.row.col.f32.f16.f16.f32 "
        "{%0,%1,%2,%3},{%4,%5,%6,%7},{%8,%9},{%0,%1,%2,%3};"
        : "+f"(c[0]), "+f"(c[1]), "+f"(c[2]), "+f"(c[3])
        : "r"(a[0]), "r"(a[1]), "r"(a[2]), "r"(a[3]), "r"(b0), "r"(b1));
}

// fp32 -> fp16 hi/lo split (A side); hi-only round (B side)
__device__ __forceinline__ void split2h(float2 v, __half2& h, __half2& l) {
    h = __float22half2_rn(v);
    float2 r = make_float2(v.x - __half2float(__low2half(h)),
                           v.y - __half2float(__high2half(h)));
    l = __float22half2_rn(r);
}
__device__ __forceinline__ void stage8a(__half* dh, __half* dl,
                                        float4 f0, float4 f1) {
    __half2 h[4], l[4];
    split2h(make_float2(f0.x, f0.y), h[0], l[0]);
    split2h(make_float2(f0.z, f0.w), h[1], l[1]);
    split2h(make_float2(f1.x, f1.y), h[2], l[2]);
    split2h(make_float2(f1.z, f1.w), h[3], l[3]);
    *(uint4*)dh = *(uint4*)h;
    *(uint4*)dl = *(uint4*)l;
}
__device__ __forceinline__ void stage8b(__half* dh, float4 f0, float4 f1) {
    __half2 h[4];
    h[0] = __float22half2_rn(make_float2(f0.x, f0.y));
    h[1] = __float22half2_rn(make_float2(f0.z, f0.w));
    h[2] = __float22half2_rn(make_float2(f1.x, f1.y));
    h[3] = __float22half2_rn(make_float2(f1.z, f1.w));
    *(uint4*)dh = *(uint4*)h;
}

// ---------------- BK=32 smem geometry (dynamic smem) -------------------------
#define APX 40          // A pitch in halfs (80B rows -> conflict-free ldmatrix)
#define BPX 136         // B pitch in halfs (272B rows -> conflict-free trans)
#define AH_SZ (2*64*APX)       // per-field elems, 2 buffers (A hi, A lo)
#define BH_SZ (2*32*BPX)       // B hi only, 2 buffers
#define SMEM_BYTES ((2*AH_SZ + BH_SZ) * 2)   // 37888 B

// one k16 substep (ks in {0,1}); warp layout wm:{0,1} x wn:{0..3}, NF=4
// fp16 2-term: ah*bh + al*bh  (6 ldmatrix, 16 mma per substep)
__device__ __forceinline__ void stepX(
    const __half* Ah, const __half* Al, const __half* Bh,
    int ks, int wm, int wn, int lane, float (*acc)[4])
{
    uint32_t ah[2][4], al[2][4];
    const int arow = lane & 15, acol = (lane >> 4) * 8;
    #pragma unroll
    for (int mf = 0; mf < 2; mf++) {
        int off = (wm * 32 + mf * 16 + arow) * APX + ks * 16 + acol;
        ldm_x4(ah[mf], smem_u32(Ah + off));
        ldm_x4(al[mf], smem_u32(Al + off));
    }
    const int bkr = lane & 15;
    const int bnl = (lane >> 4) * 8;
    #pragma unroll
    for (int nf2 = 0; nf2 < 2; nf2++) {
        int off = (ks * 16 + bkr) * BPX + wn * 32 + nf2 * 16 + bnl;
        uint32_t bh[4];
        ldm_x4t(bh, smem_u32(Bh + off));
        #pragma unroll
        for (int mf = 0; mf < 2; mf++) {
            float* c0 = acc[mf * 4 + nf2 * 2 + 0];
            float* c1 = acc[mf * 4 + nf2 * 2 + 1];
            mma_f16(c0, ah[mf], bh[0], bh[1]);
            mma_f16(c0, al[mf], bh[0], bh[1]);
            mma_f16(c1, ah[mf], bh[2], bh[3]);
            mma_f16(c1, al[mf], bh[2], bh[3]);
        }
    }
}

#define GEMM_PREAMBLE \
    extern __shared__ __half dsm[]; \
    __half* sAh = dsm; \
    __half* sAl = dsm + AH_SZ; \
    __half* sBh = dsm + 2 * AH_SZ; \
    const int tid = threadIdx.x, lane = tid & 31, wid = tid >> 5; \
    const int wm = wid & 1, wn = wid >> 1; \
    const int ar = tid >> 2, akc = (tid & 3) * 8; \
    const int bk = tid >> 4, bnc = (tid & 15) * 8; \
    float acc[8][4]; \
    _Pragma("unroll") for (int i = 0; i < 8; i++) \
        _Pragma("unroll") for (int j = 0; j < 4; j++) acc[i][j] = 0.f;

#define A_AT(buf, r, c)  (sAh + (buf) * (64 * APX) + (r) * APX + (c))
#define AL_AT(buf, r, c) (sAl + (buf) * (64 * APX) + (r) * APX + (c))
#define B_AT(buf, r, c)  (sBh + (buf) * (32 * BPX) + (r) * BPX + (c))

#define STORE_A(buf) \
    stage8a(A_AT(buf, ar, akc), AL_AT(buf, ar, akc), fa0, fa1);
#define STORE_B1(buf) \
    stage8b(B_AT(buf, bk, bnc), fb0, fb1);
#define STORE_B2(buf) \
    stage8b(B_AT(buf, bk + 16, bnc), fb0, fb1);

#define LOAD_B1(k0) \
    fb0 = *(const float4*)(Bg + (size_t)(k0) * N); \
    fb1 = *(const float4*)(Bg + (size_t)(k0) * N + 4);
#define LOAD_B2(k0) \
    fb0 = *(const float4*)(Bg + (size_t)((k0) + 16) * N); \
    fb1 = *(const float4*)(Bg + (size_t)((k0) + 16) * N + 4);

#define MAINLOOP(LOAD_A) \
    __syncthreads(); \
    const int nK = Kd >> 5; \
    int buf = 0; \
    for (int kt = 0; kt < nK; kt++) { \
        const bool nxt = (kt + 1) < nK; \
        const int k0 = (kt + 1) << 5; \
        if (nxt) { LOAD_A(k0); LOAD_B1(k0); } \
        stepX(A_AT(buf,0,0), AL_AT(buf,0,0), B_AT(buf,0,0), 0, wm, wn, lane, acc); \
        if (nxt) { int nb = buf ^ 1; STORE_A(nb); STORE_B1(nb); LOAD_B2(k0); } \
        stepX(A_AT(buf,0,0), AL_AT(buf,0,0), B_AT(buf,0,0), 1, wm, wn, lane, acc); \
        if (nxt) { int nb = buf ^ 1; STORE_B2(nb); } \
        __syncthreads(); \
        buf ^= 1; \
    }

#define PROLOGUE(LOAD_A) \
    float4 fa0, fa1, fb0, fb1; \
    LOAD_A(0) STORE_A(0) \
    LOAD_B1(0) STORE_B1(0) \
    LOAD_B2(0) STORE_B2(0)

// ============================================================================
// Batched dense GEMM: C[z] = A @ B[z]. BM=64, BN=128, BK=32.
// ============================================================================
#define LOADA_PLAIN(k0) \
    fa0 = *(const float4*)(Ag + (k0)); fa1 = *(const float4*)(Ag + (k0) + 4);

__global__ __launch_bounds__(256, 3)
void mma_d64_batch(const float* __restrict__ A, const float* __restrict__ Bw,
                   float* __restrict__ C, int Kd, int N,
                   size_t bStride, size_t cStride)
{
    GEMM_PREAMBLE
    const int m0 = blockIdx.y * 64, n0 = blockIdx.x * 128;
    const float* Bz = Bw + (size_t)blockIdx.z * bStride;
    float* Cz = C + (size_t)blockIdx.z * cStride;
    const float* Ag = A + (size_t)(m0 + ar) * Kd + akc;
    const float* Bg = Bz + (size_t)bk * N + n0 + bnc;

    PROLOGUE(LOADA_PLAIN)
    MAINLOOP(LOADA_PLAIN)

    #pragma unroll
    for (int mf = 0; mf < 2; mf++)
        #pragma unroll
        for (int nf = 0; nf < 4; nf++) {
            float* c = acc[mf * 4 + nf];
            int r0  = m0 + wm * 32 + mf * 16 + (lane >> 2);
            int col = n0 + wn * 32 + nf * 8 + (lane & 3) * 2;
            float* p0 = Cz + (size_t)r0 * N + col;
            float* p1 = Cz + (size_t)(r0 + 8) * N + col;
            p0[0] = c[0]; p0[1] = c[1]; p1[0] = c[2]; p1[1] = c[3];
        }
}

// ============================================================================
// Split-K dense GEMM (Wo): z halves K, partials to C + z*T*H.
// ============================================================================
__global__ __launch_bounds__(256, 3)
void mma_d64_splitk(const float* __restrict__ A, const float* __restrict__ Bw,
                    float* __restrict__ C, int KdFull, int N)
{
    GEMM_PREAMBLE
    const int m0 = blockIdx.y * 64, n0 = blockIdx.x * 128;
    const int Kd = KdFull >> 1;
    const int kOff = blockIdx.z * Kd;
    float* Cz = C + (size_t)blockIdx.z * T_ * H_;
    const float* Ag = A + (size_t)(m0 + ar) * KdFull + kOff + akc;
    const float* Bg = Bw + (size_t)(kOff + bk) * N + n0 + bnc;

    PROLOGUE(LOADA_PLAIN)
    MAINLOOP(LOADA_PLAIN)

    #pragma unroll
    for (int mf = 0; mf < 2; mf++)
        #pragma unroll
        for (int nf = 0; nf < 4; nf++) {
            float* c = acc[mf * 4 + nf];
            int r0  = m0 + wm * 32 + mf * 16 + (lane >> 2);
            int col = n0 + wn * 32 + nf * 8 + (lane & 3) * 2;
            float* p0 = Cz + (size_t)r0 * N + col;
            float* p1 = Cz + (size_t)(r0 + 8) * N + col;
            p0[0] = c[0]; p0[1] = c[1]; p1[0] = c[2]; p1[1] = c[3];
        }
}

// ============================================================================
// Shared-expert down GEMM (fused SwiGLU A), batched over z=e.
// ============================================================================
#define LOADA_SWI(k0) { \
    float4 gg0 = *(const float4*)(Gg + (k0)), gg1 = *(const float4*)(Gg + (k0) + 4); \
    float4 uu0 = *(const float4*)(Gg + (k0) + I_), uu1 = *(const float4*)(Gg + (k0) + I_ + 4); \
    fa0 = make_float4(silu1(gg0.x)*uu0.x, silu1(gg0.y)*uu0.y, silu1(gg0.z)*uu0.z, silu1(gg0.w)*uu0.w); \
    fa1 = make_float4(silu1(gg1.x)*uu1.x, silu1(gg1.y)*uu1.y, silu1(gg1.z)*uu1.z, silu1(gg1.w)*uu1.w); }

__global__ __launch_bounds__(256, 3)
void mma_shared_down(const float* __restrict__ Wd_s)
{
    GEMM_PREAMBLE
    const int N = H_, Kd = I_;
    const int m0 = blockIdx.y * 64, n0 = blockIdx.x * 128;
    const int e = blockIdx.z;
    const float* Gg = g_sgu + (size_t)e * T_ * 2 * I_ + (size_t)(m0 + ar) * (2 * I_) + akc;
    const float* Bg = Wd_s + (size_t)e * I_ * H_ + (size_t)bk * N + n0 + bnc;
    float* Cz = g_sdwn + (size_t)e * T_ * H_;

    PROLOGUE(LOADA_SWI)
    MAINLOOP(LOADA_SWI)

    #pragma unroll
    for (int mf = 0; mf < 2; mf++)
        #pragma unroll
        for (int nf = 0; nf < 4; nf++) {
            float* c = acc[mf * 4 + nf];
            int r0  = m0 + wm * 32 + mf * 16 + (lane >> 2);
            int col = n0 + wn * 32 + nf * 8 + (lane & 3) * 2;
            float* p0 = Cz + (size_t)r0 * N + col;
            float* p1 = Cz + (size_t)(r0 + 8) * N + col;
            p0[0] = c[0]; p0[1] = c[1]; p1[0] = c[2]; p1[1] = c[3];
        }
}

// ============================================================================
// Routed up GEMM: gathered A rows from g_h1. grid=(2I/128, T/64, E).
// ============================================================================
#define LOADA_GATH(k0) \
    fa0 = (tok >= 0) ? *(const float4*)(Ag + (k0)) : make_float4(0.f,0.f,0.f,0.f); \
    fa1 = (tok >= 0) ? *(const float4*)(Ag + (k0) + 4) : make_float4(0.f,0.f,0.f,0.f);

__global__ __launch_bounds__(256, 3)
void mma_up_routed(const float* __restrict__ Wgu)
{
    const int e = blockIdx.z;
    const int cnt = g_cnt[e];
    const int m0 = blockIdx.y * 64;
    if (m0 >= cnt) return;
    GEMM_PREAMBLE
    const int off = g_off[e];
    const int n0 = blockIdx.x * 128;
    const int N = 2 * I_, Kd = H_;
    const int tok = (m0 + ar < cnt) ? g_ltok[off + m0 + ar] : -1;
    const float* Ag = (tok >= 0) ? (g_h1 + (size_t)tok * H_ + akc) : g_h1;
    const float* Bg = Wgu + (size_t)e * H_ * 2 * I_ + (size_t)bk * N + n0 + bnc;

    PROLOGUE(LOADA_GATH)
    MAINLOOP(LOADA_GATH)

    #pragma unroll
    for (int mf = 0; mf < 2; mf++)
        #pragma unroll
        for (int nf = 0; nf < 4; nf++) {
            float* c = acc[mf * 4 + nf];
            int lr0 = m0 + wm * 32 + mf * 16 + (lane >> 2);
            int col = n0 + wn * 32 + nf * 8 + (lane & 3) * 2;
            if (lr0 < cnt) {
                float* p = g_rgu + (size_t)(off + lr0) * N + col;
                p[0] = c[0]; p[1] = c[1];
            }
            if (lr0 + 8 < cnt) {
                float* p = g_rgu + (size_t)(off + lr0 + 8) * N + col;
                p[0] = c[2]; p[1] = c[3];
            }
        }
}

// ============================================================================
// Routed down GEMM: fused SwiGLU A from g_rgu, weighted scatter epilogue.
// ============================================================================
#define LOADA_SWIR(k0) \
    if (aok) { \
        float4 gg0 = *(const float4*)(Ag + (k0)), gg1 = *(const float4*)(Ag + (k0) + 4); \
        float4 uu0 = *(const float4*)(Ag + (k0) + I_), uu1 = *(const float4*)(Ag + (k0) + I_ + 4); \
        fa0 = make_float4(silu1(gg0.x)*uu0.x, silu1(gg0.y)*uu0.y, silu1(gg0.z)*uu0.z, silu1(gg0.w)*uu0.w); \
        fa1 = make_float4(silu1(gg1.x)*uu1.x, silu1(gg1.y)*uu1.y, silu1(gg1.z)*uu1.z, silu1(gg1.w)*uu1.w); \
    } else { fa0 = fa1 = make_float4(0.f,0.f,0.f,0.f); }

__global__ __launch_bounds__(256, 3)
void mma_down_routed(const float* __restrict__ Wd)
{
    const int e = blockIdx.z;
    const int cnt = g_cnt[e];
    const int m0 = blockIdx.y * 64;
    if (m0 >= cnt) return;
    GEMM_PREAMBLE
    const int off = g_off[e];
    const int n0 = blockIdx.x * 128;
    const int N = H_, Kd = I_;
    const bool aok = (m0 + ar) < cnt;
    const float* Ag = g_rgu + (size_t)(off + (aok ? m0 + ar : 0)) * (2 * I_) + akc;
    const float* Bg = Wd + (size_t)e * I_ * H_ + (size_t)bk * N + n0 + bnc;

    PROLOGUE(LOADA_SWIR)
    MAINLOOP(LOADA_SWIR)

    #pragma unroll
    for (int mf = 0; mf < 2; mf++)
        #pragma unroll
        for (int nf = 0; nf < 4; nf++) {
            float* c = acc[mf * 4 + nf];
            int lr0 = m0 + wm * 32 + mf * 16 + (lane >> 2);
            int col = n0 + wn * 32 + nf * 8 + (lane & 3) * 2;
            if (lr0 < cnt) {
                int slot = g_lslot[off + lr0];
                float w  = g_lw[off + lr0];
                float* p = g_rdwn + (size_t)slot * H_ + col;
                p[0] = w * c[0]; p[1] = w * c[1];
            }
            if (lr0 + 8 < cnt) {
                int slot = g_lslot[off + lr0 + 8];
                float w  = g_lw[off + lr0 + 8];
                float* p = g_rdwn + (size_t)slot * H_ + col;
                p[0] = w * c[2]; p[1] = w * c[3];
            }
        }
}

// ---------------- flash attention (fp32, validated) --------------------------
__global__ __launch_bounds__(256)
void flash_attn() {
    __shared__ float Qs[64][68];
    __shared__ float Ks[32][68];
    __shared__ float Vs[32][68];
    __shared__ float Ps[64][36];
    const int q0 = blockIdx.x * 64;
    const int h  = blockIdx.y;
    const int b  = blockIdx.z;
    const int tid = threadIdx.x;
    const size_t rs = 3 * H_;
    const float* qb = g_qkv + (size_t)b * S_ * rs + (size_t)h * HD_;
    const float* kb = qb + H_;
    const float* vb = qb + 2 * H_;
    const float scale = 0.125f;
    for (int i = tid; i < 64 * 64; i += 256) {
        int r = i >> 6, d = i & 63;
        Qs[r][d] = qb[(size_t)(q0 + r) * rs + d] * scale;
    }
    const int r  = tid >> 2;
    const int c4 = tid & 3;
    float m_i = -1e30f, l_i = 0.f;
    float acc[16];
    #pragma unroll
    for (int i = 0; i < 16; i++) acc[i] = 0.f;
    __syncthreads();
    for (int kt = 0; kt < S_; kt += 32) {
        for (int i = tid; i < 32 * 64; i += 256) {
            int rr = i >> 6, d = i & 63;
            Ks[rr][d] = kb[(size_t)(kt + rr) * rs + d];
            Vs[rr][d] = vb[(size_t)(kt + rr) * rs + d];
        }
        __syncthreads();
        float sc[8];
        float mx = -1e30f;
        const float4* qrow = (const float4*)&Qs[r][0];
        #pragma unroll
        for (int jj = 0; jj < 8; jj++) {
            int j = c4 * 8 + jj;
            const float4* krow = (const float4*)&Ks[j][0];
            float sv = 0.f;
            #pragma unroll
            for (int dv = 0; dv < 16; dv++) {
                float4 a = qrow[dv], bq = krow[dv];
                sv += a.x * bq.x + a.y * bq.y + a.z * bq.z + a.w * bq.w;
            }
            sc[jj] = sv; mx = fmaxf(mx, sv);
        }
        mx = fmaxf(mx, __shfl_xor_sync(0xffffffffu, mx, 1));
        mx = fmaxf(mx, __shfl_xor_sync(0xffffffffu, mx, 2));
        float m_new = fmaxf(m_i, mx);
        float alpha = expf(m_i - m_new);
        float psum = 0.f;
        #pragma unroll
        for (int jj = 0; jj < 8; jj++) {
            float p = expf(sc[jj] - m_new);
            Ps[r][c4 * 8 + jj] = p;
            psum += p;
        }
        psum += __shfl_xor_sync(0xffffffffu, psum, 1);
        psum += __shfl_xor_sync(0xffffffffu, psum, 2);
        l_i = l_i * alpha + psum;
        m_i = m_new;
        #pragma unroll
        for (int i = 0; i < 16; i++) acc[i] *= alpha;
        __syncwarp();
        #pragma unroll
        for (int i = 0; i < 16; i++) {
            int d = c4 * 16 + i;
            float s = 0.f;
            #pragma unroll 8
            for (int j = 0; j < 32; j++) s += Ps[r][j] * Vs[j][d];
            acc[i] += s;
        }
        __syncthreads();
    }
    float inv = 1.f / l_i;
    float* ob = g_attn + (size_t)((b * S_ + q0 + r)) * H_ + (size_t)h * HD_;
    #pragma unroll
    for (int i = 0; i < 16; i++) ob[c4 * 16 + i] = acc[i] * inv;
}

// ---------------- residual + rmsnorm over 3-way sum --------------------------
__global__ __launch_bounds__(256)
void resid_rms3(const float* __restrict__ a, const float* __restrict__ b0,
                const float* __restrict__ b1, float* __restrict__ o) {
    const int t = blockIdx.x;
    float v[4]; float ss = 0.f;
    #pragma unroll
    for (int i = 0; i < 4; i++) {
        int j = i * 256 + threadIdx.x;
        float s = a[(size_t)t * H_ + j] + b0[(size_t)t * H_ + j] + b1[(size_t)t * H_ + j];
        v[i] = s; ss += s * s;
    }
    ss = block_sum256(ss);
    float inv = rsqrtf(ss * (1.f / H_) + EPS_);
    #pragma unroll
    for (int i = 0; i < 4; i++) {
        int j = i * 256 + threadIdx.x;
        o[(size_t)t * H_ + j] = v[i] * inv;
    }
}

// ---------------- routing ----------------------------------------------------
__global__ void zero_small() {
    int i = threadIdx.x;
    if (i < E_) { g_Pi[i] = 0.f; g_cnt[i] = 0; }
    if (i < D_)   g_comm[i] = 0.f;
}

__global__ void routing_kernel(const float* __restrict__ Wr) {
    const int t = blockIdx.x;
    const int e = threadIdx.x;
    const float* xr = g_h1 + (size_t)t * H_;
    float logit = 0.f;
    for (int j = 0; j < H_; j++) logit += xr[j] * Wr[(size_t)j * E_ + e];
    float m = logit;
    #pragma unroll
    for (int o = 16; o; o >>= 1) m = fmaxf(m, __shfl_xor_sync(0xffffffffu, m, o));
    float ex = expf(logit - m);
    float s = ex;
    #pragma unroll
    for (int o = 16; o; o >>= 1) s += __shfl_xor_sync(0xffffffffu, s, o);
    float prob = ex / s;
    atomicAdd(&g_Pi[e], prob);
    __shared__ float sp[E_];
    sp[e] = prob;
    __syncwarp();
    if (e == 0) {
        float ds[D_];
        #pragma unroll
        for (int d = 0; d < D_; d++)
            ds[d] = sp[4*d] + sp[4*d+1] + sp[4*d+2] + sp[4*d+3];
        bool dsel[D_] = {};
        for (int rsel = 0; rsel < KD_; rsel++) {
            int best = -1; float bv = -1e30f;
            for (int d = 0; d < D_; d++)
                if (!dsel[d] && ds[d] > bv) { bv = ds[d]; best = d; }
            dsel[best] = true;
        }
        float masked[E_];
        #pragma unroll
        for (int i = 0; i < E_; i++)
            masked[i] = dsel[i >> 2] ? sp[i] : -1e30f;
        int   iv[K_]; float wv[K_];
        for (int rsel = 0; rsel < K_; rsel++) {
            int best = 0; float bv = -1e31f;
            for (int i = 0; i < E_; i++)
                if (masked[i] > bv) { bv = masked[i]; best = i; }
            iv[rsel] = best; wv[rsel] = bv;
            masked[best] = -1e31f;
        }
        float mm = wv[0];
        float ssum = 0.f;
        #pragma unroll
        for (int rsel = 0; rsel < K_; rsel++) { wv[rsel] = expf(wv[rsel] - mm); ssum += wv[rsel]; }
        bool hit[D_] = {};
        #pragma unroll
        for (int rsel = 0; rsel < K_; rsel++) hit[iv[rsel] >> 2] = true;
        for (int d = 0; d < D_; d++)
            if (hit[d]) atomicAdd(&g_comm[d], 1.0f);
        #pragma unroll
        for (int rsel = 0; rsel < K_; rsel++) {
            int idx = t * K_ + rsel;
            g_sel_e[idx] = iv[rsel];
            g_sel_w[idx] = wv[rsel] / ssum;
            atomicAdd(&g_cnt[iv[rsel]], 1);
        }
    }
}

__global__ void offsets_kernel() {
    if (threadIdx.x == 0) {
        int s = 0;
        for (int e = 0; e < E_; e++) { g_off[e] = s; g_cur[e] = s; s += g_cnt[e]; }
    }
}

__global__ void scatter_kernel() {
    int i = blockIdx.x * 256 + threadIdx.x;
    if (i >= TK_) return;
    int e = g_sel_e[i];
    int pos = atomicAdd(&g_cur[e], 1);
    g_ltok[pos]  = i / K_;
    g_lslot[pos] = i;
    g_lw[pos]    = g_sel_w[i];
}

// ---------------- final combine + rmsnorm + aux -------------------------------
__global__ __launch_bounds__(256)
void final_kernel(float* __restrict__ out) {
    const int t = blockIdx.x;
    float v[4]; float ss = 0.f;
    #pragma unroll
    for (int i = 0; i < 4; i++) {
        int j = i * 256 + threadIdx.x;
        float s = g_h1[(size_t)t * H_ + j]
                + g_sdwn[(size_t)t * H_ + j]
                + g_sdwn[(size_t)(T_ + t) * H_ + j];
        #pragma unroll
        for (int k = 0; k < K_; k++)
            s += g_rdwn[(size_t)(t * K_ + k) * H_ + j];
        v[i] = s; ss += s * s;
    }
    ss = block_sum256(ss);
    float inv = rsqrtf(ss * (1.f / H_) + EPS_);
    #pragma unroll
    for (int i = 0; i < 4; i++) {
        int j = i * 256 + threadIdx.x;
        out[(size_t)t * H_ + j] = v[i] * inv;
    }
}

__global__ void aux_kernel(float* out, int out_size) {
    if (out_size <= T_ * H_) return;
    const float fTK = (float)TK_ + 1e-10f;
    float fi[E_], Pi[E_];
    float s1 = 0.f;
    for (int e = 0; e < E_; e++) {
        fi[e] = (float)g_cnt[e] / fTK;
        Pi[e] = g_Pi[e] / (float)T_;
        s1 += fi[e] * Pi[e];
    }
    float eb = fminf(s1 * 0.003f, 10.f);
    float dP[D_];
    float s2 = 0.f;
    for (int d = 0; d < D_; d++) {
        float df = (fi[4*d] + fi[4*d+1] + fi[4*d+2] + fi[4*d+3]) * 0.25f;
        dP[d]    = Pi[4*d] + Pi[4*d+1] + Pi[4*d+2] + Pi[4*d+3];
        s2 += df * dP[d];
    }
    float db = fminf(s2 * 0.05f, 10.f);
    float s3 = 0.f;
    for (int d = 0; d < D_; d++) {
        float fc = g_comm[d] / ((float)(T_ * KD_) + 1e-10f);
        s3 += fc * dP[d];
    }
    float cb = fminf(s3 * 0.02f, 10.f);
    out[T_ * H_] = eb + db + cb;
}

// ---------------- host driver -------------------------------------------------
extern "C" void kernel_launch(void* const* d_in, const int* in_sizes, int n_in,
                              void* d_out, int out_size) {
    const float* x     = (const float*)d_in[0];
    const float* Wqkv  = (const float*)d_in[1];
    const float* Wo    = (const float*)d_in[2];
    const float* Wgu_s = (const float*)d_in[3];
    const float* Wd_s  = (const float*)d_in[4];
    const float* Wr    = (const float*)d_in[5];
    const float* Wgu   = (const float*)d_in[6];
    const float* Wd    = (const float*)d_in[7];
    float* out = (float*)d_out;

    float *p_qkv, *p_attn, *p_tmp, *p_h1, *p_sgu;
    cudaGetSymbolAddress((void**)&p_qkv,  g_qkv);
    cudaGetSymbolAddress((void**)&p_attn, g_attn);
    cudaGetSymbolAddress((void**)&p_tmp,  g_tmp);
    cudaGetSymbolAddress((void**)&p_h1,   g_h1);
    cudaGetSymbolAddress((void**)&p_sgu,  g_sgu);

    static bool init_done = false;
    static cudaStream_t s1;
    static cudaEvent_t evFork, evJoin;
    if (!init_done) {
        cudaFuncSetAttribute(mma_d64_batch,   cudaFuncAttributeMaxDynamicSharedMemorySize, SMEM_BYTES);
        cudaFuncSetAttribute(mma_d64_splitk,  cudaFuncAttributeMaxDynamicSharedMemorySize, SMEM_BYTES);
        cudaFuncSetAttribute(mma_shared_down, cudaFuncAttributeMaxDynamicSharedMemorySize, SMEM_BYTES);
        cudaFuncSetAttribute(mma_up_routed,   cudaFuncAttributeMaxDynamicSharedMemorySize, SMEM_BYTES);
        cudaFuncSetAttribute(mma_down_routed, cudaFuncAttributeMaxDynamicSharedMemorySize, SMEM_BYTES);
        cudaStreamCreateWithFlags(&s1, cudaStreamNonBlocking);
        cudaEventCreateWithFlags(&evFork, cudaEventDisableTiming);
        cudaEventCreateWithFlags(&evJoin, cudaEventDisableTiming);
        init_done = true;
    }

    zero_small<<<1, 64>>>();

    // qkv = x @ Wqkv
    mma_d64_batch<<<dim3(3 * H_ / 128, T_ / 64, 1), 256, SMEM_BYTES>>>(
        x, Wqkv, p_qkv, H_, 3 * H_, 0, 0);

    // attention
    flash_attn<<<dim3(S_ / 64, NH_, B_), 256>>>();

    // Wo split-K=2 ; h1 = rmsnorm(x + tmp0 + tmp1)
    mma_d64_splitk<<<dim3(H_ / 128, T_ / 64, 2), 256, SMEM_BYTES>>>(
        p_attn, Wo, p_tmp, H_, H_);
    resid_rms3<<<T_, 256>>>(x, p_tmp, p_tmp + (size_t)T_ * H_, p_h1);

    // fork: shared-expert chain on s1, routed chain on main stream
    cudaEventRecord(evFork, 0);
    cudaStreamWaitEvent(s1, evFork, 0);

    mma_d64_batch<<<dim3(2 * I_ / 128, T_ / 64, 2), 256, SMEM_BYTES, s1>>>(
        p_h1, Wgu_s, p_sgu, H_, 2 * I_,
        (size_t)H_ * 2 * I_, (size_t)T_ * 2 * I_);
    mma_shared_down<<<dim3(H_ / 128, T_ / 64, 2), 256, SMEM_BYTES, s1>>>(Wd_s);
    cudaEventRecord(evJoin, s1);

    routing_kernel<<<T_, 32>>>(Wr);
    offsets_kernel<<<1, 32>>>();
    scatter_kernel<<<(TK_ + 255) / 256, 256>>>();
    mma_up_routed<<<dim3(2 * I_ / 128, T_ / 64, E_), 256, SMEM_BYTES>>>(Wgu);
    mma_down_routed<<<dim3(H_ / 128, T_ / 64, E_), 256, SMEM_BYTES>>>(Wd);

    // join and finish
    cudaStreamWaitEvent(0, evJoin, 0);
    final_kernel<<<T_, 256>>>(out);
    aux_kernel<<<1, 1>>>(out, out_size);
}

// round 16
// speedup vs baseline: 2.4211x; 1.0488x over previous
#include <cuda_runtime.h>
#include <cuda_fp16.h>
#include <math.h>
#include <stdint.h>

// ---------------- problem constants ----------------
#define B_   2
#define S_   512
#define T_   1024
#define H_   1024
#define NH_  16
#define HD_  64
#define E_   32
#define D_   8
#define K_   6
#define KD_  3
#define I_   1536
#define EPS_ 1e-5f
#define TK_  (T_*K_)

// ---------------- device scratch ----------------
__device__ float g_qkv [T_*3*H_];
__device__ float g_attn[T_*H_];
__device__ float g_tmp [2*T_*H_];
__device__ float g_h1  [T_*H_];
__device__ float g_sgu [2*T_*2*I_];
__device__ float g_sdwn[2*T_*H_];
__device__ float g_rgu [TK_*2*I_];
__device__ float g_rdwn[TK_*H_];

__device__ float g_Pi  [E_];
__device__ float g_comm[D_];
__device__ int   g_cnt [E_];
__device__ int   g_off [E_];
__device__ int   g_cur [E_];
__device__ int   g_sel_e[TK_];
__device__ float g_sel_w[TK_];
__device__ int   g_ltok [TK_];
__device__ int   g_lslot[TK_];
__device__ float g_lw   [TK_];

__device__ __forceinline__ float silu1(float g) { return g / (1.f + expf(-g)); }

__device__ __forceinline__ float block_sum256(float v) {
    __shared__ float red[8];
    __shared__ float tot;
    #pragma unroll
    for (int o = 16; o; o >>= 1) v += __shfl_xor_sync(0xffffffffu, v, o);
    if ((threadIdx.x & 31) == 0) red[threadIdx.x >> 5] = v;
    __syncthreads();
    if (threadIdx.x < 8) {
        float s = red[threadIdx.x];
        #pragma unroll
        for (int o = 4; o; o >>= 1) s += __shfl_xor_sync(0xffu, s, o);
        if (threadIdx.x == 0) tot = s;
    }
    __syncthreads();
    return tot;
}

// ---------------- mma/ldmatrix primitives -----------------------------------
__device__ __forceinline__ uint32_t smem_u32(const void* p) {
    return (uint32_t)__cvta_generic_to_shared(p);
}
__device__ __forceinline__ void ldm_x4(uint32_t r[4], uint32_t addr) {
    asm volatile("ldmatrix.sync.aligned.m8n8.x4.shared.b16 {%0,%1,%2,%3},[%4];"
        : "=r"(r[0]), "=r"(r[1]), "=r"(r[2]), "=r"(r[3]) : "r"(addr));
}
__device__ __forceinline__ void ldm_x4t(uint32_t r[4], uint32_t addr) {
    asm volatile("ldmatrix.sync.aligned.m8n8.x4.trans.shared.b16 {%0,%1,%2,%3},[%4];"
        : "=r"(r[0]), "=r"(r[1]), "=r"(r[2]), "=r"(r[3]) : "r"(addr));
}
__device__ __forceinline__ void mma_f16(float c[4], const uint32_t a[4],
                                        uint32_t b0, uint32_t b1) {
    asm volatile(
        "mma.sync.aligned.m16n8k16.row.col.f32.f16.f16.f32 "
        "{%0,%1,%2,%3},{%4,%5,%6,%7},{%8,%9},{%0,%1,%2,%3};"
        : "+f"(c[0]), "+f"(c[1]), "+f"(c[2]), "+f"(c[3])
        : "r"(a[0]), "r"(a[1]), "r"(a[2]), "r"(a[3]), "r"(b0), "r"(b1));
}

// fp32 -> fp16 round (both operands, single-term)
__device__ __forceinline__ void stage8h(__half* dh, float4 f0, float4 f1) {
    __half2 h[4];
    h[0] = __float22half2_rn(make_float2(f0.x, f0.y));
    h[1] = __float22half2_rn(make_float2(f0.z, f0.w));
    h[2] = __float22half2_rn(make_float2(f1.x, f1.y));
    h[3] = __float22half2_rn(make_float2(f1.z, f1.w));
    *(uint4*)dh = *(uint4*)h;
}

// ---------------- BK=32 smem geometry (dynamic smem) -------------------------
#define APX 40          // A pitch in halfs (80B rows -> conflict-free ldmatrix)
#define BPX 136         // B pitch in halfs (272B rows -> conflict-free trans)
#define AH_SZ (2*64*APX)       // A hi only, 2 buffers
#define BH_SZ (2*32*BPX)       // B hi only, 2 buffers
#define SMEM_BYTES ((AH_SZ + BH_SZ) * 2)   // 27648 B

// one k16 substep (ks in {0,1}); warp layout wm:{0,1} x wn:{0..3}, NF=4
// pure fp16: ah*bh (4 ldmatrix, 8 mma per substep)
__device__ __forceinline__ void stepX(
    const __half* Ah, const __half* Bh,
    int ks, int wm, int wn, int lane, float (*acc)[4])
{
    uint32_t ah[2][4];
    const int arow = lane & 15, acol = (lane >> 4) * 8;
    #pragma unroll
    for (int mf = 0; mf < 2; mf++) {
        int off = (wm * 32 + mf * 16 + arow) * APX + ks * 16 + acol;
        ldm_x4(ah[mf], smem_u32(Ah + off));
    }
    const int bkr = lane & 15;
    const int bnl = (lane >> 4) * 8;
    #pragma unroll
    for (int nf2 = 0; nf2 < 2; nf2++) {
        int off = (ks * 16 + bkr) * BPX + wn * 32 + nf2 * 16 + bnl;
        uint32_t bh[4];
        ldm_x4t(bh, smem_u32(Bh + off));
        #pragma unroll
        for (int mf = 0; mf < 2; mf++) {
            float* c0 = acc[mf * 4 + nf2 * 2 + 0];
            float* c1 = acc[mf * 4 + nf2 * 2 + 1];
            mma_f16(c0, ah[mf], bh[0], bh[1]);
            mma_f16(c1, ah[mf], bh[2], bh[3]);
        }
    }
}

#define GEMM_PREAMBLE \
    extern __shared__ __half dsm[]; \
    __half* sAh = dsm; \
    __half* sBh = dsm + AH_SZ; \
    const int tid = threadIdx.x, lane = tid & 31, wid = tid >> 5; \
    const int wm = wid & 1, wn = wid >> 1; \
    const int ar = tid >> 2, akc = (tid & 3) * 8; \
    const int bk = tid >> 4, bnc = (tid & 15) * 8; \
    float acc[8][4]; \
    _Pragma("unroll") for (int i = 0; i < 8; i++) \
        _Pragma("unroll") for (int j = 0; j < 4; j++) acc[i][j] = 0.f;

#define A_AT(buf, r, c)  (sAh + (buf) * (64 * APX) + (r) * APX + (c))
#define B_AT(buf, r, c)  (sBh + (buf) * (32 * BPX) + (r) * BPX + (c))

#define STORE_A(buf) \
    stage8h(A_AT(buf, ar, akc), fa0, fa1);
#define STORE_B1(buf) \
    stage8h(B_AT(buf, bk, bnc), fb0, fb1);
#define STORE_B2(buf) \
    stage8h(B_AT(buf, bk + 16, bnc), fb0, fb1);

#define LOAD_B1(k0) \
    fb0 = *(const float4*)(Bg + (size_t)(k0) * N); \
    fb1 = *(const float4*)(Bg + (size_t)(k0) * N + 4);
#define LOAD_B2(k0) \
    fb0 = *(const float4*)(Bg + (size_t)((k0) + 16) * N); \
    fb1 = *(const float4*)(Bg + (size_t)((k0) + 16) * N + 4);

#define MAINLOOP(LOAD_A) \
    __syncthreads(); \
    const int nK = Kd >> 5; \
    int buf = 0; \
    for (int kt = 0; kt < nK; kt++) { \
        const bool nxt = (kt + 1) < nK; \
        const int k0 = (kt + 1) << 5; \
        if (nxt) { LOAD_A(k0); LOAD_B1(k0); } \
        stepX(A_AT(buf,0,0), B_AT(buf,0,0), 0, wm, wn, lane, acc); \
        if (nxt) { int nb = buf ^ 1; STORE_A(nb); STORE_B1(nb); LOAD_B2(k0); } \
        stepX(A_AT(buf,0,0), B_AT(buf,0,0), 1, wm, wn, lane, acc); \
        if (nxt) { int nb = buf ^ 1; STORE_B2(nb); } \
        __syncthreads(); \
        buf ^= 1; \
    }

#define PROLOGUE(LOAD_A) \
    float4 fa0, fa1, fb0, fb1; \
    LOAD_A(0) STORE_A(0) \
    LOAD_B1(0) STORE_B1(0) \
    LOAD_B2(0) STORE_B2(0)

// ============================================================================
// Batched dense GEMM: C[z] = A @ B[z]. BM=64, BN=128, BK=32.
// ============================================================================
#define LOADA_PLAIN(k0) \
    fa0 = *(const float4*)(Ag + (k0)); fa1 = *(const float4*)(Ag + (k0) + 4);

__global__ __launch_bounds__(256, 3)
void mma_d64_batch(const float* __restrict__ A, const float* __restrict__ Bw,
                   float* __restrict__ C, int Kd, int N,
                   size_t bStride, size_t cStride)
{
    GEMM_PREAMBLE
    const int m0 = blockIdx.y * 64, n0 = blockIdx.x * 128;
    const float* Bz = Bw + (size_t)blockIdx.z * bStride;
    float* Cz = C + (size_t)blockIdx.z * cStride;
    const float* Ag = A + (size_t)(m0 + ar) * Kd + akc;
    const float* Bg = Bz + (size_t)bk * N + n0 + bnc;

    PROLOGUE(LOADA_PLAIN)
    MAINLOOP(LOADA_PLAIN)

    #pragma unroll
    for (int mf = 0; mf < 2; mf++)
        #pragma unroll
        for (int nf = 0; nf < 4; nf++) {
            float* c = acc[mf * 4 + nf];
            int r0  = m0 + wm * 32 + mf * 16 + (lane >> 2);
            int col = n0 + wn * 32 + nf * 8 + (lane & 3) * 2;
            float* p0 = Cz + (size_t)r0 * N + col;
            float* p1 = Cz + (size_t)(r0 + 8) * N + col;
            p0[0] = c[0]; p0[1] = c[1]; p1[0] = c[2]; p1[1] = c[3];
        }
}

// ============================================================================
// Split-K dense GEMM (Wo): z halves K, partials to C + z*T*H.
// ============================================================================
__global__ __launch_bounds__(256, 3)
void mma_d64_splitk(const float* __restrict__ A, const float* __restrict__ Bw,
                    float* __restrict__ C, int KdFull, int N)
{
    GEMM_PREAMBLE
    const int m0 = blockIdx.y * 64, n0 = blockIdx.x * 128;
    const int Kd = KdFull >> 1;
    const int kOff = blockIdx.z * Kd;
    float* Cz = C + (size_t)blockIdx.z * T_ * H_;
    const float* Ag = A + (size_t)(m0 + ar) * KdFull + kOff + akc;
    const float* Bg = Bw + (size_t)(kOff + bk) * N + n0 + bnc;

    PROLOGUE(LOADA_PLAIN)
    MAINLOOP(LOADA_PLAIN)

    #pragma unroll
    for (int mf = 0; mf < 2; mf++)
        #pragma unroll
        for (int nf = 0; nf < 4; nf++) {
            float* c = acc[mf * 4 + nf];
            int r0  = m0 + wm * 32 + mf * 16 + (lane >> 2);
            int col = n0 + wn * 32 + nf * 8 + (lane & 3) * 2;
            float* p0 = Cz + (size_t)r0 * N + col;
            float* p1 = Cz + (size_t)(r0 + 8) * N + col;
            p0[0] = c[0]; p0[1] = c[1]; p1[0] = c[2]; p1[1] = c[3];
        }
}

// ============================================================================
// Shared-expert down GEMM (fused SwiGLU A), batched over z=e.
// ============================================================================
#define LOADA_SWI(k0) { \
    float4 gg0 = *(const float4*)(Gg + (k0)), gg1 = *(const float4*)(Gg + (k0) + 4); \
    float4 uu0 = *(const float4*)(Gg + (k0) + I_), uu1 = *(const float4*)(Gg + (k0) + I_ + 4); \
    fa0 = make_float4(silu1(gg0.x)*uu0.x, silu1(gg0.y)*uu0.y, silu1(gg0.z)*uu0.z, silu1(gg0.w)*uu0.w); \
    fa1 = make_float4(silu1(gg1.x)*uu1.x, silu1(gg1.y)*uu1.y, silu1(gg1.z)*uu1.z, silu1(gg1.w)*uu1.w); }

__global__ __launch_bounds__(256, 3)
void mma_shared_down(const float* __restrict__ Wd_s)
{
    GEMM_PREAMBLE
    const int N = H_, Kd = I_;
    const int m0 = blockIdx.y * 64, n0 = blockIdx.x * 128;
    const int e = blockIdx.z;
    const float* Gg = g_sgu + (size_t)e * T_ * 2 * I_ + (size_t)(m0 + ar) * (2 * I_) + akc;
    const float* Bg = Wd_s + (size_t)e * I_ * H_ + (size_t)bk * N + n0 + bnc;
    float* Cz = g_sdwn + (size_t)e * T_ * H_;

    PROLOGUE(LOADA_SWI)
    MAINLOOP(LOADA_SWI)

    #pragma unroll
    for (int mf = 0; mf < 2; mf++)
        #pragma unroll
        for (int nf = 0; nf < 4; nf++) {
            float* c = acc[mf * 4 + nf];
            int r0  = m0 + wm * 32 + mf * 16 + (lane >> 2);
            int col = n0 + wn * 32 + nf * 8 + (lane & 3) * 2;
            float* p0 = Cz + (size_t)r0 * N + col;
            float* p1 = Cz + (size_t)(r0 + 8) * N + col;
            p0[0] = c[0]; p0[1] = c[1]; p1[0] = c[2]; p1[1] = c[3];
        }
}

// ============================================================================
// Routed up GEMM: gathered A rows from g_h1. grid=(2I/128, T/64, E).
// ============================================================================
#define LOADA_GATH(k0) \
    fa0 = (tok >= 0) ? *(const float4*)(Ag + (k0)) : make_float4(0.f,0.f,0.f,0.f); \
    fa1 = (tok >= 0) ? *(const float4*)(Ag + (k0) + 4) : make_float4(0.f,0.f,0.f,0.f);

__global__ __launch_bounds__(256, 3)
void mma_up_routed(const float* __restrict__ Wgu)
{
    const int e = blockIdx.z;
    const int cnt = g_cnt[e];
    const int m0 = blockIdx.y * 64;
    if (m0 >= cnt) return;
    GEMM_PREAMBLE
    const int off = g_off[e];
    const int n0 = blockIdx.x * 128;
    const int N = 2 * I_, Kd = H_;
    const int tok = (m0 + ar < cnt) ? g_ltok[off + m0 + ar] : -1;
    const float* Ag = (tok >= 0) ? (g_h1 + (size_t)tok * H_ + akc) : g_h1;
    const float* Bg = Wgu + (size_t)e * H_ * 2 * I_ + (size_t)bk * N + n0 + bnc;

    PROLOGUE(LOADA_GATH)
    MAINLOOP(LOADA_GATH)

    #pragma unroll
    for (int mf = 0; mf < 2; mf++)
        #pragma unroll
        for (int nf = 0; nf < 4; nf++) {
            float* c = acc[mf * 4 + nf];
            int lr0 = m0 + wm * 32 + mf * 16 + (lane >> 2);
            int col = n0 + wn * 32 + nf * 8 + (lane & 3) * 2;
            if (lr0 < cnt) {
                float* p = g_rgu + (size_t)(off + lr0) * N + col;
                p[0] = c[0]; p[1] = c[1];
            }
            if (lr0 + 8 < cnt) {
                float* p = g_rgu + (size_t)(off + lr0 + 8) * N + col;
                p[0] = c[2]; p[1] = c[3];
            }
        }
}

// ============================================================================
// Routed down GEMM: fused SwiGLU A from g_rgu, weighted scatter epilogue.
// ============================================================================
#define LOADA_SWIR(k0) \
    if (aok) { \
        float4 gg0 = *(const float4*)(Ag + (k0)), gg1 = *(const float4*)(Ag + (k0) + 4); \
        float4 uu0 = *(const float4*)(Ag + (k0) + I_), uu1 = *(const float4*)(Ag + (k0) + I_ + 4); \
        fa0 = make_float4(silu1(gg0.x)*uu0.x, silu1(gg0.y)*uu0.y, silu1(gg0.z)*uu0.z, silu1(gg0.w)*uu0.w); \
        fa1 = make_float4(silu1(gg1.x)*uu1.x, silu1(gg1.y)*uu1.y, silu1(gg1.z)*uu1.z, silu1(gg1.w)*uu1.w); \
    } else { fa0 = fa1 = make_float4(0.f,0.f,0.f,0.f); }

__global__ __launch_bounds__(256, 3)
void mma_down_routed(const float* __restrict__ Wd)
{
    const int e = blockIdx.z;
    const int cnt = g_cnt[e];
    const int m0 = blockIdx.y * 64;
    if (m0 >= cnt) return;
    GEMM_PREAMBLE
    const int off = g_off[e];
    const int n0 = blockIdx.x * 128;
    const int N = H_, Kd = I_;
    const bool aok = (m0 + ar) < cnt;
    const float* Ag = g_rgu + (size_t)(off + (aok ? m0 + ar : 0)) * (2 * I_) + akc;
    const float* Bg = Wd + (size_t)e * I_ * H_ + (size_t)bk * N + n0 + bnc;

    PROLOGUE(LOADA_SWIR)
    MAINLOOP(LOADA_SWIR)

    #pragma unroll
    for (int mf = 0; mf < 2; mf++)
        #pragma unroll
        for (int nf = 0; nf < 4; nf++) {
            float* c = acc[mf * 4 + nf];
            int lr0 = m0 + wm * 32 + mf * 16 + (lane >> 2);
            int col = n0 + wn * 32 + nf * 8 + (lane & 3) * 2;
            if (lr0 < cnt) {
                int slot = g_lslot[off + lr0];
                float w  = g_lw[off + lr0];
                float* p = g_rdwn + (size_t)slot * H_ + col;
                p[0] = w * c[0]; p[1] = w * c[1];
            }
            if (lr0 + 8 < cnt) {
                int slot = g_lslot[off + lr0 + 8];
                float w  = g_lw[off + lr0 + 8];
                float* p = g_rdwn + (size_t)slot * H_ + col;
                p[0] = w * c[2]; p[1] = w * c[3];
            }
        }
}

// ---------------- flash attention (fp32, validated) --------------------------
__global__ __launch_bounds__(256)
void flash_attn() {
    __shared__ float Qs[64][68];
    __shared__ float Ks[32][68];
    __shared__ float Vs[32][68];
    __shared__ float Ps[64][36];
    const int q0 = blockIdx.x * 64;
    const int h  = blockIdx.y;
    const int b  = blockIdx.z;
    const int tid = threadIdx.x;
    const size_t rs = 3 * H_;
    const float* qb = g_qkv + (size_t)b * S_ * rs + (size_t)h * HD_;
    const float* kb = qb + H_;
    const float* vb = qb + 2 * H_;
    const float scale = 0.125f;
    for (int i = tid; i < 64 * 64; i += 256) {
        int r = i >> 6, d = i & 63;
        Qs[r][d] = qb[(size_t)(q0 + r) * rs + d] * scale;
    }
    const int r  = tid >> 2;
    const int c4 = tid & 3;
    float m_i = -1e30f, l_i = 0.f;
    float acc[16];
    #pragma unroll
    for (int i = 0; i < 16; i++) acc[i] = 0.f;
    __syncthreads();
    for (int kt = 0; kt < S_; kt += 32) {
        for (int i = tid; i < 32 * 64; i += 256) {
            int rr = i >> 6, d = i & 63;
            Ks[rr][d] = kb[(size_t)(kt + rr) * rs + d];
            Vs[rr][d] = vb[(size_t)(kt + rr) * rs + d];
        }
        __syncthreads();
        float sc[8];
        float mx = -1e30f;
        const float4* qrow = (const float4*)&Qs[r][0];
        #pragma unroll
        for (int jj = 0; jj < 8; jj++) {
            int j = c4 * 8 + jj;
            const float4* krow = (const float4*)&Ks[j][0];
            float sv = 0.f;
            #pragma unroll
            for (int dv = 0; dv < 16; dv++) {
                float4 a = qrow[dv], bq = krow[dv];
                sv += a.x * bq.x + a.y * bq.y + a.z * bq.z + a.w * bq.w;
            }
            sc[jj] = sv; mx = fmaxf(mx, sv);
        }
        mx = fmaxf(mx, __shfl_xor_sync(0xffffffffu, mx, 1));
        mx = fmaxf(mx, __shfl_xor_sync(0xffffffffu, mx, 2));
        float m_new = fmaxf(m_i, mx);
        float alpha = expf(m_i - m_new);
        float psum = 0.f;
        #pragma unroll
        for (int jj = 0; jj < 8; jj++) {
            float p = expf(sc[jj] - m_new);
            Ps[r][c4 * 8 + jj] = p;
            psum += p;
        }
        psum += __shfl_xor_sync(0xffffffffu, psum, 1);
        psum += __shfl_xor_sync(0xffffffffu, psum, 2);
        l_i = l_i * alpha + psum;
        m_i = m_new;
        #pragma unroll
        for (int i = 0; i < 16; i++) acc[i] *= alpha;
        __syncwarp();
        #pragma unroll
        for (int i = 0; i < 16; i++) {
            int d = c4 * 16 + i;
            float s = 0.f;
            #pragma unroll 8
            for (int j = 0; j < 32; j++) s += Ps[r][j] * Vs[j][d];
            acc[i] += s;
        }
        __syncthreads();
    }
    float inv = 1.f / l_i;
    float* ob = g_attn + (size_t)((b * S_ + q0 + r)) * H_ + (size_t)h * HD_;
    #pragma unroll
    for (int i = 0; i < 16; i++) ob[c4 * 16 + i] = acc[i] * inv;
}

// ---------------- residual + rmsnorm over 3-way sum --------------------------
__global__ __launch_bounds__(256)
void resid_rms3(const float* __restrict__ a, const float* __restrict__ b0,
                const float* __restrict__ b1, float* __restrict__ o) {
    const int t = blockIdx.x;
    float v[4]; float ss = 0.f;
    #pragma unroll
    for (int i = 0; i < 4; i++) {
        int j = i * 256 + threadIdx.x;
        float s = a[(size_t)t * H_ + j] + b0[(size_t)t * H_ + j] + b1[(size_t)t * H_ + j];
        v[i] = s; ss += s * s;
    }
    ss = block_sum256(ss);
    float inv = rsqrtf(ss * (1.f / H_) + EPS_);
    #pragma unroll
    for (int i = 0; i < 4; i++) {
        int j = i * 256 + threadIdx.x;
        o[(size_t)t * H_ + j] = v[i] * inv;
    }
}

// ---------------- routing ----------------------------------------------------
__global__ void zero_small() {
    int i = threadIdx.x;
    if (i < E_) { g_Pi[i] = 0.f; g_cnt[i] = 0; }
    if (i < D_)   g_comm[i] = 0.f;
}

__global__ void routing_kernel(const float* __restrict__ Wr) {
    const int t = blockIdx.x;
    const int e = threadIdx.x;
    const float* xr = g_h1 + (size_t)t * H_;
    float logit = 0.f;
    for (int j = 0; j < H_; j++) logit += xr[j] * Wr[(size_t)j * E_ + e];
    float m = logit;
    #pragma unroll
    for (int o = 16; o; o >>= 1) m = fmaxf(m, __shfl_xor_sync(0xffffffffu, m, o));
    float ex = expf(logit - m);
    float s = ex;
    #pragma unroll
    for (int o = 16; o; o >>= 1) s += __shfl_xor_sync(0xffffffffu, s, o);
    float prob = ex / s;
    atomicAdd(&g_Pi[e], prob);
    __shared__ float sp[E_];
    sp[e] = prob;
    __syncwarp();
    if (e == 0) {
        float ds[D_];
        #pragma unroll
        for (int d = 0; d < D_; d++)
            ds[d] = sp[4*d] + sp[4*d+1] + sp[4*d+2] + sp[4*d+3];
        bool dsel[D_] = {};
        for (int rsel = 0; rsel < KD_; rsel++) {
            int best = -1; float bv = -1e30f;
            for (int d = 0; d < D_; d++)
                if (!dsel[d] && ds[d] > bv) { bv = ds[d]; best = d; }
            dsel[best] = true;
        }
        float masked[E_];
        #pragma unroll
        for (int i = 0; i < E_; i++)
            masked[i] = dsel[i >> 2] ? sp[i] : -1e30f;
        int   iv[K_]; float wv[K_];
        for (int rsel = 0; rsel < K_; rsel++) {
            int best = 0; float bv = -1e31f;
            for (int i = 0; i < E_; i++)
                if (masked[i] > bv) { bv = masked[i]; best = i; }
            iv[rsel] = best; wv[rsel] = bv;
            masked[best] = -1e31f;
        }
        float mm = wv[0];
        float ssum = 0.f;
        #pragma unroll
        for (int rsel = 0; rsel < K_; rsel++) { wv[rsel] = expf(wv[rsel] - mm); ssum += wv[rsel]; }
        bool hit[D_] = {};
        #pragma unroll
        for (int rsel = 0; rsel < K_; rsel++) hit[iv[rsel] >> 2] = true;
        for (int d = 0; d < D_; d++)
            if (hit[d]) atomicAdd(&g_comm[d], 1.0f);
        #pragma unroll
        for (int rsel = 0; rsel < K_; rsel++) {
            int idx = t * K_ + rsel;
            g_sel_e[idx] = iv[rsel];
            g_sel_w[idx] = wv[rsel] / ssum;
            atomicAdd(&g_cnt[iv[rsel]], 1);
        }
    }
}

__global__ void offsets_kernel() {
    if (threadIdx.x == 0) {
        int s = 0;
        for (int e = 0; e < E_; e++) { g_off[e] = s; g_cur[e] = s; s += g_cnt[e]; }
    }
}

__global__ void scatter_kernel() {
    int i = blockIdx.x * 256 + threadIdx.x;
    if (i >= TK_) return;
    int e = g_sel_e[i];
    int pos = atomicAdd(&g_cur[e], 1);
    g_ltok[pos]  = i / K_;
    g_lslot[pos] = i;
    g_lw[pos]    = g_sel_w[i];
}

// ---------------- final combine + rmsnorm + aux -------------------------------
__global__ __launch_bounds__(256)
void final_kernel(float* __restrict__ out) {
    const int t = blockIdx.x;
    float v[4]; float ss = 0.f;
    #pragma unroll
    for (int i = 0; i < 4; i++) {
        int j = i * 256 + threadIdx.x;
        float s = g_h1[(size_t)t * H_ + j]
                + g_sdwn[(size_t)t * H_ + j]
                + g_sdwn[(size_t)(T_ + t) * H_ + j];
        #pragma unroll
        for (int k = 0; k < K_; k++)
            s += g_rdwn[(size_t)(t * K_ + k) * H_ + j];
        v[i] = s; ss += s * s;
    }
    ss = block_sum256(ss);
    float inv = rsqrtf(ss * (1.f / H_) + EPS_);
    #pragma unroll
    for (int i = 0; i < 4; i++) {
        int j = i * 256 + threadIdx.x;
        out[(size_t)t * H_ + j] = v[i] * inv;
    }
}

__global__ void aux_kernel(float* out, int out_size) {
    if (out_size <= T_ * H_) return;
    const float fTK = (float)TK_ + 1e-10f;
    float fi[E_], Pi[E_];
    float s1 = 0.f;
    for (int e = 0; e < E_; e++) {
        fi[e] = (float)g_cnt[e] / fTK;
        Pi[e] = g_Pi[e] / (float)T_;
        s1 += fi[e] * Pi[e];
    }
    float eb = fminf(s1 * 0.003f, 10.f);
    float dP[D_];
    float s2 = 0.f;
    for (int d = 0; d < D_; d++) {
        float df = (fi[4*d] + fi[4*d+1] + fi[4*d+2] + fi[4*d+3]) * 0.25f;
        dP[d]    = Pi[4*d] + Pi[4*d+1] + Pi[4*d+2] + Pi[4*d+3];
        s2 += df * dP[d];
    }
    float db = fminf(s2 * 0.05f, 10.f);
    float s3 = 0.f;
    for (int d = 0; d < D_; d++) {
        float fc = g_comm[d] / ((float)(T_ * KD_) + 1e-10f);
        s3 += fc * dP[d];
    }
    float cb = fminf(s3 * 0.02f, 10.f);
    out[T_ * H_] = eb + db + cb;
}

// ---------------- host driver -------------------------------------------------
extern "C" void kernel_launch(void* const* d_in, const int* in_sizes, int n_in,
                              void* d_out, int out_size) {
    const float* x     = (const float*)d_in[0];
    const float* Wqkv  = (const float*)d_in[1];
    const float* Wo    = (const float*)d_in[2];
    const float* Wgu_s = (const float*)d_in[3];
    const float* Wd_s  = (const float*)d_in[4];
    const float* Wr    = (const float*)d_in[5];
    const float* Wgu   = (const float*)d_in[6];
    const float* Wd    = (const float*)d_in[7];
    float* out = (float*)d_out;

    float *p_qkv, *p_attn, *p_tmp, *p_h1, *p_sgu;
    cudaGetSymbolAddress((void**)&p_qkv,  g_qkv);
    cudaGetSymbolAddress((void**)&p_attn, g_attn);
    cudaGetSymbolAddress((void**)&p_tmp,  g_tmp);
    cudaGetSymbolAddress((void**)&p_h1,   g_h1);
    cudaGetSymbolAddress((void**)&p_sgu,  g_sgu);

    static bool init_done = false;
    static cudaStream_t s1;
    static cudaEvent_t evFork, evJoin;
    if (!init_done) {
        cudaFuncSetAttribute(mma_d64_batch,   cudaFuncAttributeMaxDynamicSharedMemorySize, SMEM_BYTES);
        cudaFuncSetAttribute(mma_d64_splitk,  cudaFuncAttributeMaxDynamicSharedMemorySize, SMEM_BYTES);
        cudaFuncSetAttribute(mma_shared_down, cudaFuncAttributeMaxDynamicSharedMemorySize, SMEM_BYTES);
        cudaFuncSetAttribute(mma_up_routed,   cudaFuncAttributeMaxDynamicSharedMemorySize, SMEM_BYTES);
        cudaFuncSetAttribute(mma_down_routed, cudaFuncAttributeMaxDynamicSharedMemorySize, SMEM_BYTES);
        cudaStreamCreateWithFlags(&s1, cudaStreamNonBlocking);
        cudaEventCreateWithFlags(&evFork, cudaEventDisableTiming);
        cudaEventCreateWithFlags(&evJoin, cudaEventDisableTiming);
        init_done = true;
    }

    zero_small<<<1, 64>>>();

    // qkv = x @ Wqkv
    mma_d64_batch<<<dim3(3 * H_ / 128, T_ / 64, 1), 256, SMEM_BYTES>>>(
        x, Wqkv, p_qkv, H_, 3 * H_, 0, 0);

    // attention
    flash_attn<<<dim3(S_ / 64, NH_, B_), 256>>>();

    // Wo split-K=2 ; h1 = rmsnorm(x + tmp0 + tmp1)
    mma_d64_splitk<<<dim3(H_ / 128, T_ / 64, 2), 256, SMEM_BYTES>>>(
        p_attn, Wo, p_tmp, H_, H_);
    resid_rms3<<<T_, 256>>>(x, p_tmp, p_tmp + (size_t)T_ * H_, p_h1);

    // fork: shared-expert chain on s1, routed chain on main stream
    cudaEventRecord(evFork, 0);
    cudaStreamWaitEvent(s1, evFork, 0);

    mma_d64_batch<<<dim3(2 * I_ / 128, T_ / 64, 2), 256, SMEM_BYTES, s1>>>(
        p_h1, Wgu_s, p_sgu, H_, 2 * I_,
        (size_t)H_ * 2 * I_, (size_t)T_ * 2 * I_);
    mma_shared_down<<<dim3(H_ / 128, T_ / 64, 2), 256, SMEM_BYTES, s1>>>(Wd_s);
    cudaEventRecord(evJoin, s1);

    routing_kernel<<<T_, 32>>>(Wr);
    offsets_kernel<<<1, 32>>>();
    scatter_kernel<<<(TK_ + 255) / 256, 256>>>();
    mma_up_routed<<<dim3(2 * I_ / 128, T_ / 64, E_), 256, SMEM_BYTES>>>(Wgu);
    mma_down_routed<<<dim3(H_ / 128, T_ / 64, E_), 256, SMEM_BYTES>>>(Wd);

    // join and finish
    cudaStreamWaitEvent(0, evJoin, 0);
    final_kernel<<<T_, 256>>>(out);
    aux_kernel<<<1, 1>>>(out, out_size);
}